// round 5
// baseline (speedup 1.0000x reference)
#include <cuda_runtime.h>
#include <cuda_bf16.h>
#include <cstdint>

// Problem constants
#define TT 500
#define BB 32
#define INF 512
#define HH 1024
#define G4 4096
#define H2 2048

// gx: [dir][t][b][jp(512)][gate(4)][jj(2)]
__device__ float g_gxp[(size_t)2 * TT * BB * G4];
// A packed in HMMA fragment order: uint4 per (dir, ct64, wid4, kA128, lane32)
// kA covers k' 0..2047: seg0 = w_hi (k 0..1023), seg1 = w_lo
__device__ uint4 g_ap[2 * 64 * 4 * 128 * 32];
// h packed in HMMA B-fragment order: [buf][dir][kstep128][half2][lane32] uint4
// kstep 0..63 = h_hi, 64..127 = h_lo
__device__ uint4 g_hp[2 * 2 * 128 * 2 * 32];
// cell state: [dir][b][j]
__device__ float g_c[2 * BB * HH];

__device__ __forceinline__ float hsig(float x) {
    return fminf(fmaxf(0.2f * x + 0.5f, 0.0f), 1.0f);
}
__device__ __forceinline__ float htanh(float x) {
    return fminf(fmaxf(x, -1.0f), 1.0f);
}

__device__ __forceinline__ void mma16816(float* c, const uint4& a,
                                         uint32_t b0, uint32_t b1) {
    asm volatile(
        "mma.sync.aligned.m16n8k16.row.col.f32.bf16.bf16.f32 "
        "{%0,%1,%2,%3}, {%4,%5,%6,%7}, {%8,%9}, {%0,%1,%2,%3};"
        : "+f"(c[0]), "+f"(c[1]), "+f"(c[2]), "+f"(c[3])
        : "r"(a.x), "r"(a.y), "r"(a.z), "r"(a.w), "r"(b0), "r"(b1));
}

// ---------------------------------------------------------------------------
// Prepack w_hh into A-fragment layout. 2^21 threads, one uint4 each.
// id = (((dir*64+ct)*4+wid)*128 + kA)*32 + lane
// lane=(g,t): a0=(row g, k0..k0+1), a1=(row g+8, k0), a2=(g, k0+8), a3=(g+8, k0+8)
// row_global = ct*64 + wid*16 + g(+8);  row = j*4+gate
// ---------------------------------------------------------------------------
__global__ void prepack_a(const float* __restrict__ whh_f,
                          const float* __restrict__ whh_r) {
    const int id = blockIdx.x * blockDim.x + threadIdx.x;
    const int lane = id & 31;
    const int kA = (id >> 5) & 127;
    const int wid = (id >> 12) & 3;
    const int ct = (id >> 14) & 63;
    const int dir = id >> 20;
    const float* __restrict__ w = dir ? whh_r : whh_f;
    const int g = lane >> 2, tq = lane & 3;
    const int rbase = ct * 64 + wid * 16 + g;
    const int k0 = kA * 16 + 2 * tq;

    uint32_t outw[4];
#pragma unroll
    for (int pos = 0; pos < 4; ++pos) {
        const int row = rbase + (pos & 1) * 8;
        const int kk = k0 + (pos >> 1) * 8;
        const int j = row >> 2, gate = row & 3;
        const float* wrow = w + (size_t)(gate * HH + j) * HH;
        uint32_t halves[2];
#pragma unroll
        for (int e = 0; e < 2; ++e) {
            const int kq = kk + e;
            const int seg = kq >> 10;
            const float v = wrow[kq & 1023];
            const __nv_bfloat16 hi = __float2bfloat16(v);
            const __nv_bfloat16 val =
                seg ? __float2bfloat16(v - __bfloat162float(hi)) : hi;
            halves[e] = (uint32_t)__bfloat16_as_ushort(val);
        }
        outw[pos] = halves[0] | (halves[1] << 16);
    }
    g_ap[id] = make_uint4(outw[0], outw[1], outw[2], outw[3]);
}

// ---------------------------------------------------------------------------
__global__ void init_kernel() {
    const int id = blockIdx.x * blockDim.x + threadIdx.x;
    if (id < 2 * 2 * 128 * 2 * 32) g_hp[id] = make_uint4(0u, 0u, 0u, 0u);
    if (id < 2 * BB * HH) g_c[id] = 0.0f;
}

// ---------------------------------------------------------------------------
// Input GEMM (fp32 SIMT, unchanged math): writes [dir][t][b][jp][gate][jj]
// ---------------------------------------------------------------------------
__global__ void gemm_gx_kernel(const float* __restrict__ x,
                               const float* __restrict__ wih_f,
                               const float* __restrict__ wih_r,
                               const float* __restrict__ bih_f,
                               const float* __restrict__ bhh_f,
                               const float* __restrict__ bih_r,
                               const float* __restrict__ bhh_r) {
    const int dir = blockIdx.z;
    const float* __restrict__ w  = dir ? wih_r : wih_f;
    const float* __restrict__ b1 = dir ? bih_r : bih_f;
    const float* __restrict__ b2 = dir ? bhh_r : bhh_f;
    float* __restrict__ gx = g_gxp + (size_t)dir * TT * BB * G4;

    const int m0 = blockIdx.y * 64;
    const int n0 = blockIdx.x * 64;

    __shared__ float As[16][64];
    __shared__ float Bs[16][64];

    const int tid = threadIdx.x;
    const int tx = tid & 15;
    const int ty = tid >> 4;

    float acc[4][4] = {};

    for (int k0 = 0; k0 < INF; k0 += 16) {
        {
            const int row = tid >> 2;
            const int kq  = tid & 3;
            float4 va = *(const float4*)&x[(size_t)(m0 + row) * INF + k0 + kq * 4];
            As[kq * 4 + 0][row] = va.x;
            As[kq * 4 + 1][row] = va.y;
            As[kq * 4 + 2][row] = va.z;
            As[kq * 4 + 3][row] = va.w;
            float4 vb = *(const float4*)&w[(size_t)(n0 + row) * INF + k0 + kq * 4];
            Bs[kq * 4 + 0][row] = vb.x;
            Bs[kq * 4 + 1][row] = vb.y;
            Bs[kq * 4 + 2][row] = vb.z;
            Bs[kq * 4 + 3][row] = vb.w;
        }
        __syncthreads();
#pragma unroll
        for (int kk = 0; kk < 16; ++kk) {
            float4 a = *(float4*)&As[kk][ty * 4];
            float4 bb = *(float4*)&Bs[kk][tx * 4];
            float av[4] = {a.x, a.y, a.z, a.w};
            float bv[4] = {bb.x, bb.y, bb.z, bb.w};
#pragma unroll
            for (int i = 0; i < 4; ++i)
#pragma unroll
                for (int jn = 0; jn < 4; ++jn)
                    acc[i][jn] = fmaf(av[i], bv[jn], acc[i][jn]);
        }
        __syncthreads();
    }

    const int mbase = m0 + ty * 4;
    const int t = mbase >> 5;
    const int b0 = mbase & 31;
#pragma unroll
    for (int jn2 = 0; jn2 < 2; ++jn2) {
        const int n = n0 + tx * 4 + jn2 * 2;
        const int gate = n >> 10;
        const int j0 = n & 1023;            // even
        const int jp = j0 >> 1;
        const float bias0 = b1[n] + b2[n];
        const float bias1 = b1[n + 1] + b2[n + 1];
#pragma unroll
        for (int i = 0; i < 4; ++i) {
            float2 v = make_float2(acc[i][jn2 * 2] + bias0,
                                   acc[i][jn2 * 2 + 1] + bias1);
            *(float2*)&gx[(((size_t)t * BB + b0 + i) * 512 + jp) * 8 + gate * 2] = v;
        }
    }
}

// ---------------------------------------------------------------------------
// One recurrent step via mma.sync. grid = 128 CTAs (2 dirs x 64 row-tiles of
// 64 rows), 128 threads (4 warps, warp-tile 16x32).
// K' = 3072 in 3 segments; A stream reuses seg0 data for seg2, B (h) reuses
// hi data for seg1. No smem in mainloop; D staged via smem for epilogue.
// ---------------------------------------------------------------------------
__global__ void __launch_bounds__(128)
lstm_step(float* __restrict__ out, int t) {
    __shared__ float sD[64][33];
    const int tid = threadIdx.x;
    const int lane = tid & 31;
    const int wid = tid >> 5;
    const int dir = blockIdx.x >> 6;
    const int ct = blockIdx.x & 63;
    const int tr = dir ? (TT - 1 - t) : t;
    const int rb = t & 1, wb = 1 - rb;

    const uint4* __restrict__ Ap =
        g_ap + ((size_t)((dir * 64 + ct) * 4 + wid) * 128) * 32 + lane;
    const uint4* __restrict__ Bp =
        g_hp + ((size_t)(rb * 2 + dir) * 128) * 2 * 32 + lane;

    float acc[4][4] = {};

    // seg0: kA=i, kB=i (hi*hi) | seg1: kA=64+i, kB=i (lo*hi) | seg2: kA=i, kB=64+i
#pragma unroll 1
    for (int seg = 0; seg < 3; ++seg) {
        const uint4* ApS = Ap + (seg == 1 ? 64 * 32 : 0);
        const uint4* BpS = Bp + (seg == 2 ? 64 * 2 * 32 : 0);
#pragma unroll 8
        for (int i = 0; i < 64; ++i) {
            uint4 a  = __ldg(ApS + i * 32);
            uint4 bA = __ldg(BpS + (i * 2) * 32);
            uint4 bB = __ldg(BpS + (i * 2 + 1) * 32);
            mma16816(acc[0], a, bA.x, bA.y);
            mma16816(acc[1], a, bA.z, bA.w);
            mma16816(acc[2], a, bB.x, bB.y);
            mma16816(acc[3], a, bB.z, bB.w);
        }
    }

    // D -> smem. lane=(g,tq): rows wid*16+g(+8), cols nt*8+2tq(+1)
    {
        const int g = lane >> 2, tq = lane & 3;
#pragma unroll
        for (int nt = 0; nt < 4; ++nt) {
            sD[wid * 16 + g][nt * 8 + 2 * tq] = acc[nt][0];
            sD[wid * 16 + g][nt * 8 + 2 * tq + 1] = acc[nt][1];
            sD[wid * 16 + g + 8][nt * 8 + 2 * tq] = acc[nt][2];
            sD[wid * 16 + g + 8][nt * 8 + 2 * tq + 1] = acc[nt][3];
        }
    }
    __syncthreads();

    // Epilogue: 256 slots = 8 jpairs x 32 batches, 2 per thread.
    uint32_t* __restrict__ hpw = reinterpret_cast<uint32_t*>(g_hp);
#pragma unroll
    for (int s = 0; s < 2; ++s) {
        const int sid = s * 128 + tid;
        const int b = sid & 31;
        const int jp = sid >> 5;            // 0..7
        const int jl0 = jp * 2;
        const int jg = ct * 16 + jl0;       // global j (even)

        const float* gxs =
            &g_gxp[((((size_t)dir * TT + tr) * BB + b) * 512 + (ct * 8 + jp)) * 8];
        float4 x0 = *(const float4*)gxs;        // (i,j0)(i,j1)(f,j0)(f,j1)
        float4 x1 = *(const float4*)(gxs + 4);  // (c,j0)(c,j1)(o,j0)(o,j1)
        float2 cc = *(float2*)&g_c[((size_t)dir * BB + b) * HH + jg];

        const float i0 = hsig(sD[jl0 * 4 + 0][b] + x0.x);
        const float f0 = hsig(sD[jl0 * 4 + 1][b] + x0.z);
        const float g0 = htanh(sD[jl0 * 4 + 2][b] + x1.x);
        const float o0 = hsig(sD[jl0 * 4 + 3][b] + x1.z);
        const float c0 = f0 * cc.x + i0 * g0;
        const float h0 = o0 * htanh(c0);

        const float i1 = hsig(sD[jl0 * 4 + 4][b] + x0.y);
        const float f1 = hsig(sD[jl0 * 4 + 5][b] + x0.w);
        const float g1 = htanh(sD[jl0 * 4 + 6][b] + x1.y);
        const float o1 = hsig(sD[jl0 * 4 + 7][b] + x1.w);
        const float c1 = f1 * cc.y + i1 * g1;
        const float h1 = o1 * htanh(c1);

        *(float2*)&g_c[((size_t)dir * BB + b) * HH + jg] = make_float2(c0, c1);
        *(float2*)&out[((size_t)tr * BB + b) * H2 + dir * HH + jg] =
            make_float2(h0, h1);

        // h -> B-fragment layout (hi + lo)
        const __nv_bfloat16 h0h = __float2bfloat16(h0);
        const __nv_bfloat16 h1h = __float2bfloat16(h1);
        const uint32_t hiw = (uint32_t)__bfloat16_as_ushort(h0h) |
                             ((uint32_t)__bfloat16_as_ushort(h1h) << 16);
        const __nv_bfloat16 l0 = __float2bfloat16(h0 - __bfloat162float(h0h));
        const __nv_bfloat16 l1 = __float2bfloat16(h1 - __bfloat162float(h1h));
        const uint32_t low = (uint32_t)__bfloat16_as_ushort(l0) |
                             ((uint32_t)__bfloat16_as_ushort(l1) << 16);

        const int ks = jg >> 4;
        const int rem = jg & 15;
        const int laneW = (b & 7) * 4 + ((rem >> 1) & 3);
        const int word = (b >> 3) * 2 + ((rem >> 3) & 1);
        const int half = word >> 2, sub = word & 3;
        const size_t dbase = ((size_t)wb * 2 + dir) * 128;
        hpw[(((dbase + ks) * 2 + half) * 32 + laneW) * 4 + sub] = hiw;
        hpw[(((dbase + 64 + ks) * 2 + half) * 32 + laneW) * 4 + sub] = low;
    }
}

// ---------------------------------------------------------------------------
// hy / cy tail.  out = [ output | hy(2,B,H) | cy(2,B,H) ]
// ---------------------------------------------------------------------------
__global__ void finalize_kernel(float* __restrict__ out) {
    const int idx = blockIdx.x * blockDim.x + threadIdx.x;
    const int j = idx & (HH - 1);
    const int b = (idx >> 10) & (BB - 1);
    const int dir = idx >> 15;

    const size_t base = (size_t)TT * BB * H2;
    float h;
    if (dir == 0)
        h = out[((size_t)(TT - 1) * BB + b) * H2 + j];
    else
        h = out[((size_t)b) * H2 + HH + j];
    out[base + ((size_t)dir * BB + b) * HH + j] = h;
    out[base + 2 * BB * HH + ((size_t)dir * BB + b) * HH + j] =
        g_c[((size_t)dir * BB + b) * HH + j];
}

// ---------------------------------------------------------------------------
extern "C" void kernel_launch(void* const* d_in, const int* in_sizes, int n_in,
                              void* d_out, int out_size) {
    const float* x     = (const float*)d_in[0];
    const float* wih_f = (const float*)d_in[1];
    const float* whh_f = (const float*)d_in[2];
    const float* bih_f = (const float*)d_in[3];
    const float* bhh_f = (const float*)d_in[4];
    const float* wih_r = (const float*)d_in[5];
    const float* whh_r = (const float*)d_in[6];
    const float* bih_r = (const float*)d_in[7];
    const float* bhh_r = (const float*)d_in[8];
    float* out = (float*)d_out;

    prepack_a<<<8192, 256>>>(whh_f, whh_r);
    init_kernel<<<64, 1024>>>();
    dim3 ggrid(G4 / 64, (TT * BB) / 64, 2);
    gemm_gx_kernel<<<ggrid, 256>>>(x, wih_f, wih_r, bih_f, bhh_f, bih_r, bhh_r);

    for (int t = 0; t < TT; ++t)
        lstm_step<<<128, 128>>>(out, t);

    finalize_kernel<<<64, 1024>>>(out);
}

// round 6
// speedup vs baseline: 3.8476x; 3.8476x over previous
#include <cuda_runtime.h>
#include <cuda_fp16.h>
#include <cstdint>

// Problem constants
#define TT 500
#define BB 32
#define INF 512
#define HH 1024
#define G4 4096
#define H2 2048

// gx: [dir][t][b][jp(512)][gate(4)][jj(2)]  fp32
__device__ float g_gxp[(size_t)2 * TT * BB * G4];
// W_hh fp16 A-fragments: [dir][mt(256)][kA(64)][lane(32)] uint4 ; row=4j+gate
__device__ uint4 g_ap[2 * 256 * 64 * 32];
// h fp16 B-fragments: [buf(2)][dir(2)][kA(64)][seg(2)][half(2)][lane(32)] uint4
__device__ uint4 g_hp[2 * 2 * 64 * 2 * 2 * 32];
// x fp16 A-fragments: [mt(1000)][kA(32)][lane(32)] uint4
__device__ uint4 g_xa[1000 * 32 * 32];
// w_ih fp16 B-fragments: [dir][nt(128)][kA(32)][half(2)][lane(32)] uint4
__device__ uint4 g_wb[2 * 128 * 32 * 2 * 32];
// cell state: [dir][b][j]
__device__ float g_c[2 * BB * HH];

__device__ __forceinline__ float hsig(float x) {
    return fminf(fmaxf(0.2f * x + 0.5f, 0.0f), 1.0f);
}
__device__ __forceinline__ float htanh(float x) {
    return fminf(fmaxf(x, -1.0f), 1.0f);
}
__device__ __forceinline__ void mma16816(float* c, const uint4& a,
                                         uint32_t b0, uint32_t b1) {
    asm volatile(
        "mma.sync.aligned.m16n8k16.row.col.f32.f16.f16.f32 "
        "{%0,%1,%2,%3}, {%4,%5,%6,%7}, {%8,%9}, {%0,%1,%2,%3};"
        : "+f"(c[0]), "+f"(c[1]), "+f"(c[2]), "+f"(c[3])
        : "r"(a.x), "r"(a.y), "r"(a.z), "r"(a.w), "r"(b0), "r"(b1));
}
__device__ __forceinline__ uint32_t smaddr(const void* p) {
    uint32_t a;
    asm("{ .reg .u64 t; cvta.to.shared.u64 t, %1; cvt.u32.u64 %0, t; }"
        : "=r"(a) : "l"(p));
    return a;
}
__device__ __forceinline__ void cpa16(uint32_t s, const void* g) {
    asm volatile("cp.async.cg.shared.global [%0], [%1], 16;" :: "r"(s), "l"(g));
}
__device__ __forceinline__ void cpa_commit() {
    asm volatile("cp.async.commit_group;");
}
template <int N>
__device__ __forceinline__ void cpa_wait() {
    asm volatile("cp.async.wait_group %0;" :: "n"(N));
}
__device__ __forceinline__ uint16_t f2h(float v) {
    return __half_as_ushort(__float2half_rn(v));
}

// ---------------------------------------------------------------------------
// Prepack w_hh -> fp16 A-fragments. 2^20 threads, one uint4 each.
// ---------------------------------------------------------------------------
__global__ void prepack_a(const float* __restrict__ whh_f,
                          const float* __restrict__ whh_r) {
    const int id = blockIdx.x * blockDim.x + threadIdx.x;
    const int lane = id & 31;
    const int kA = (id >> 5) & 63;
    const int mt = (id >> 11) & 255;
    const int dir = id >> 19;
    const float* __restrict__ w = dir ? whh_r : whh_f;
    const int g = lane >> 2, tq = lane & 3;
    const int rbase = mt * 16 + g;
    const int k0 = kA * 16 + 2 * tq;

    uint32_t outw[4];
#pragma unroll
    for (int pos = 0; pos < 4; ++pos) {
        const int row = rbase + (pos & 1) * 8;
        const int kk = k0 + (pos >> 1) * 8;
        const int j = row >> 2, gate = row & 3;
        const float* wrow = w + (size_t)(gate * HH + j) * HH;
        outw[pos] = (uint32_t)f2h(wrow[kk]) | ((uint32_t)f2h(wrow[kk + 1]) << 16);
    }
    g_ap[id] = make_uint4(outw[0], outw[1], outw[2], outw[3]);
}

// ---------------------------------------------------------------------------
// Prepack x -> fp16 A-fragments. 1,024,000 threads.
// ---------------------------------------------------------------------------
__global__ void prepack_x(const float* __restrict__ x) {
    const int id = blockIdx.x * blockDim.x + threadIdx.x;
    if (id >= 1000 * 32 * 32) return;
    const int lane = id & 31;
    const int kA = (id >> 5) & 31;
    const int mt = id >> 10;
    const int g = lane >> 2, tq = lane & 3;
    const int m0 = mt * 16 + g;
    const int k0 = kA * 16 + 2 * tq;

    uint32_t outw[4];
#pragma unroll
    for (int pos = 0; pos < 4; ++pos) {
        const int m = m0 + (pos & 1) * 8;
        const int kk = k0 + (pos >> 1) * 8;
        const float* xr = x + (size_t)m * INF;
        outw[pos] = (uint32_t)f2h(xr[kk]) | ((uint32_t)f2h(xr[kk + 1]) << 16);
    }
    g_xa[id] = make_uint4(outw[0], outw[1], outw[2], outw[3]);
}

// ---------------------------------------------------------------------------
// Prepack w_ih -> fp16 B-fragments. 2^21 threads, one uint32 word each.
// word id == dst word index: [dir][nt][kA][half][laneW][sub]
// ---------------------------------------------------------------------------
__global__ void prepack_wb(const float* __restrict__ wih_f,
                           const float* __restrict__ wih_r) {
    const int id = blockIdx.x * blockDim.x + threadIdx.x;
    const int sub = id & 3;
    const int laneW = (id >> 2) & 31;
    const int half = (id >> 7) & 1;
    const int kA = (id >> 8) & 31;
    const int nt = (id >> 13) & 127;
    const int dir = id >> 20;
    const float* __restrict__ w = dir ? wih_r : wih_f;

    const int wd = half * 4 + sub;
    const int ip = (wd & 1) * 4 + (laneW & 3);   // k-pair index 0..7
    const int nl = (wd >> 1) * 8 + (laneW >> 2); // n within 32
    const int n = nt * 32 + nl;
    const int k = kA * 16 + ip * 2;
    const float* wr = w + (size_t)n * INF;
    reinterpret_cast<uint32_t*>(g_wb)[id] =
        (uint32_t)f2h(wr[k]) | ((uint32_t)f2h(wr[k + 1]) << 16);
}

// ---------------------------------------------------------------------------
__global__ void init_kernel() {
    const int id = blockIdx.x * blockDim.x + threadIdx.x;
    if (id < 2 * 2 * 64 * 2 * 2 * 32) g_hp[id] = make_uint4(0u, 0u, 0u, 0u);
    if (id < 2 * BB * HH) g_c[id] = 0.0f;
}

// ---------------------------------------------------------------------------
// gx GEMM via fp16 mma.sync: D[m=16000, n=8192] += bias, K=512.
// grid (64 = 2dir x 32 ntiles-of-128, 125 mtiles-of-128), 256 thr (8 warps).
// Warp tile 64x32. Fragment-ordered smem staging, cp.async double buffer.
// ---------------------------------------------------------------------------
__global__ void __launch_bounds__(256)
gemm_gx(const float* __restrict__ bih_f, const float* __restrict__ bhh_f,
        const float* __restrict__ bih_r, const float* __restrict__ bhh_r) {
    extern __shared__ uint4 sm[];  // [A0(2048) A1(2048) B0(2048) B1(2048)]
    const uint32_t sbase = smaddr(sm);

    const int tid = threadIdx.x;
    const int lane = tid & 31;
    const int wid = tid >> 5;
    const int mw = wid >> 2, nw = wid & 3;
    const int dir = blockIdx.x >> 5;
    const int nti = blockIdx.x & 31;
    const int mt0 = blockIdx.y * 8;
    const int nt0 = nti * 4;

    const float* __restrict__ b1 = dir ? bih_r : bih_f;
    const float* __restrict__ b2 = dir ? bhh_r : bhh_f;
    float* __restrict__ gx = g_gxp + (size_t)dir * TT * BB * G4;

    auto load_chunk = [&](int c, int buf) {
        const int kA0 = c * 8;
#pragma unroll
        for (int i = 0; i < 8; ++i) {  // A: 2048 uint4
            const int idx = tid + i * 256;
            const int mtl = idx >> 8;
            const int kAl = (idx >> 5) & 7;
            const int l = idx & 31;
            const uint4* src = g_xa + ((size_t)(mt0 + mtl) * 32 + kA0 + kAl) * 32 + l;
            cpa16(sbase + (buf * 2048 + idx) * 16, src);
        }
#pragma unroll
        for (int i = 0; i < 8; ++i) {  // B: 2048 uint4
            const int idx = tid + i * 256;
            const int ntl = idx >> 9;
            const int kAl = (idx >> 6) & 7;
            const int hf = (idx >> 5) & 1;
            const int l = idx & 31;
            const uint4* src =
                g_wb + ((((size_t)(dir * 128 + nt0 + ntl) * 32 + kA0 + kAl) * 2 + hf)) * 32 + l;
            cpa16(sbase + (4096 + buf * 2048 + idx) * 16, src);
        }
        cpa_commit();
    };

    float acc[4][4][4] = {};

    load_chunk(0, 0);
    load_chunk(1, 1);

#pragma unroll 1
    for (int c = 0; c < 4; ++c) {
        cpa_wait<1>();
        __syncthreads();
        const int buf = c & 1;
        const uint4* Asm = sm + buf * 2048;
        const uint4* Bsm = sm + 4096 + buf * 2048;
#pragma unroll
        for (int kAl = 0; kAl < 8; ++kAl) {
            uint4 af[4];
#pragma unroll
            for (int i = 0; i < 4; ++i)
                af[i] = Asm[((mw * 4 + i) * 8 + kAl) * 32 + lane];
            uint4 bf0 = Bsm[((nw * 8 + kAl) * 2 + 0) * 32 + lane];
            uint4 bf1 = Bsm[((nw * 8 + kAl) * 2 + 1) * 32 + lane];
#pragma unroll
            for (int i = 0; i < 4; ++i) {
                mma16816(acc[i][0], af[i], bf0.x, bf0.y);
                mma16816(acc[i][1], af[i], bf0.z, bf0.w);
                mma16816(acc[i][2], af[i], bf1.x, bf1.y);
                mma16816(acc[i][3], af[i], bf1.z, bf1.w);
            }
        }
        __syncthreads();
        if (c + 2 < 4) load_chunk(c + 2, buf);
    }

    // Epilogue: add biases, store fp32 to [t][b][jp][gate][jj]
    const int g = lane >> 2, q = lane & 3;
#pragma unroll
    for (int i = 0; i < 4; ++i) {
        const int m = blockIdx.y * 128 + mw * 64 + i * 16 + g;
#pragma unroll
        for (int nt = 0; nt < 4; ++nt) {
            const int nd = nti * 128 + nw * 32 + nt * 8 + q * 2;
            const int gate = nd >> 10;
            const int j = nd & 1023;
            const int jp = j >> 1;
            const float bias0 = __ldg(&b1[nd]) + __ldg(&b2[nd]);
            const float bias1 = __ldg(&b1[nd + 1]) + __ldg(&b2[nd + 1]);
#pragma unroll
            for (int hrow = 0; hrow < 2; ++hrow) {
                const int mm = m + hrow * 8;
                const int tt = mm >> 5, bb = mm & 31;
                float2 v = make_float2(acc[i][nt][hrow * 2] + bias0,
                                       acc[i][nt][hrow * 2 + 1] + bias1);
                *(float2*)&gx[(((size_t)tt * BB + bb) * 512 + jp) * 8 + gate * 2] = v;
            }
        }
    }
}

// ---------------------------------------------------------------------------
// One recurrent step. grid = 128 CTAs (2 dirs x 64 ct of 64 rows), 128 thr.
// Warp = 16 rows (mt = ct*4+wid) x n32 (batch); K=1024 (64 kA), h split hi/lo.
// Manual 4-deep prefetch pipeline; A and B via direct LDG (B shared via L1).
// ---------------------------------------------------------------------------
__global__ void __launch_bounds__(128)
lstm_step(float* __restrict__ out, int t) {
    __shared__ float sD[64][33];
    const int tid = threadIdx.x;
    const int lane = tid & 31;
    const int wid = tid >> 5;
    const int dir = blockIdx.x >> 6;
    const int ct = blockIdx.x & 63;
    const int tr = dir ? (TT - 1 - t) : t;
    const int rb = t & 1, wb = rb ^ 1;

    const uint4* __restrict__ Ap =
        g_ap + ((size_t)(dir * 256 + ct * 4 + wid) * 64) * 32 + lane;
    const uint4* __restrict__ Bp =
        g_hp + ((size_t)(rb * 2 + dir) * 64) * 128 + lane;

    float acc[4][4] = {};

    uint4 pa[4][2];
    uint4 pb[4][2][4];

#define LOADG(slot, grp)                                                    \
    {                                                                       \
        _Pragma("unroll") for (int u = 0; u < 2; ++u) {                     \
            const int ka = (grp) * 2 + u;                                   \
            pa[slot][u] = __ldg(Ap + ka * 32);                              \
            _Pragma("unroll") for (int s2 = 0; s2 < 4; ++s2)                \
                pb[slot][u][s2] = __ldg(Bp + ka * 128 + s2 * 32);           \
        }                                                                   \
    }

#define COMPG(slot)                                                         \
    {                                                                       \
        _Pragma("unroll") for (int u = 0; u < 2; ++u) {                     \
            const uint4 a = pa[slot][u];                                    \
            mma16816(acc[0], a, pb[slot][u][0].x, pb[slot][u][0].y);        \
            mma16816(acc[1], a, pb[slot][u][0].z, pb[slot][u][0].w);        \
            mma16816(acc[2], a, pb[slot][u][1].x, pb[slot][u][1].y);        \
            mma16816(acc[3], a, pb[slot][u][1].z, pb[slot][u][1].w);        \
            mma16816(acc[0], a, pb[slot][u][2].x, pb[slot][u][2].y);        \
            mma16816(acc[1], a, pb[slot][u][2].z, pb[slot][u][2].w);        \
            mma16816(acc[2], a, pb[slot][u][3].x, pb[slot][u][3].y);        \
            mma16816(acc[3], a, pb[slot][u][3].z, pb[slot][u][3].w);        \
        }                                                                   \
    }

    LOADG(0, 0) LOADG(1, 1) LOADG(2, 2) LOADG(3, 3)

#pragma unroll 1
    for (int grp = 0; grp < 32; grp += 4) {
        COMPG(0) if (grp + 4 < 32) LOADG(0, grp + 4)
        COMPG(1) if (grp + 5 < 32) LOADG(1, grp + 5)
        COMPG(2) if (grp + 6 < 32) LOADG(2, grp + 6)
        COMPG(3) if (grp + 7 < 32) LOADG(3, grp + 7)
    }
#undef LOADG
#undef COMPG

    // D -> smem. lane=(g,tq): rows wid*16+g(+8), cols nt*8+2tq(+1)
    {
        const int g = lane >> 2, tq = lane & 3;
#pragma unroll
        for (int nt = 0; nt < 4; ++nt) {
            sD[wid * 16 + g][nt * 8 + 2 * tq] = acc[nt][0];
            sD[wid * 16 + g][nt * 8 + 2 * tq + 1] = acc[nt][1];
            sD[wid * 16 + g + 8][nt * 8 + 2 * tq] = acc[nt][2];
            sD[wid * 16 + g + 8][nt * 8 + 2 * tq + 1] = acc[nt][3];
        }
    }
    __syncthreads();

    // Epilogue: 256 slots = 8 jpairs x 32 batches, 2 per thread.
    uint32_t* __restrict__ hpw = reinterpret_cast<uint32_t*>(g_hp);
#pragma unroll
    for (int s = 0; s < 2; ++s) {
        const int sid = s * 128 + tid;
        const int b = sid & 31;
        const int jp = sid >> 5;            // 0..7
        const int jl0 = jp * 2;
        const int jg = ct * 16 + jl0;       // global j (even)

        const float* gxs =
            &g_gxp[((((size_t)dir * TT + tr) * BB + b) * 512 + (ct * 8 + jp)) * 8];
        float4 x0 = *(const float4*)gxs;        // (i,j0)(i,j1)(f,j0)(f,j1)
        float4 x1 = *(const float4*)(gxs + 4);  // (c,j0)(c,j1)(o,j0)(o,j1)
        float2 cc = *(float2*)&g_c[((size_t)dir * BB + b) * HH + jg];

        const float i0 = hsig(sD[jl0 * 4 + 0][b] + x0.x);
        const float f0 = hsig(sD[jl0 * 4 + 1][b] + x0.z);
        const float g0 = htanh(sD[jl0 * 4 + 2][b] + x1.x);
        const float o0 = hsig(sD[jl0 * 4 + 3][b] + x1.z);
        const float c0 = f0 * cc.x + i0 * g0;
        const float h0 = o0 * htanh(c0);

        const float i1 = hsig(sD[jl0 * 4 + 4][b] + x0.y);
        const float f1 = hsig(sD[jl0 * 4 + 5][b] + x0.w);
        const float g1 = htanh(sD[jl0 * 4 + 6][b] + x1.y);
        const float o1 = hsig(sD[jl0 * 4 + 7][b] + x1.w);
        const float c1 = f1 * cc.y + i1 * g1;
        const float h1 = o1 * htanh(c1);

        *(float2*)&g_c[((size_t)dir * BB + b) * HH + jg] = make_float2(c0, c1);
        *(float2*)&out[((size_t)tr * BB + b) * H2 + dir * HH + jg] =
            make_float2(h0, h1);

        // h -> fp16 B-fragments, hi (seg0) + lo (seg1)
        const uint16_t h0h = f2h(h0);
        const uint16_t h1h = f2h(h1);
        const uint32_t hiw = (uint32_t)h0h | ((uint32_t)h1h << 16);
        const float r0 = h0 - __half2float(__ushort_as_half(h0h));
        const float r1 = h1 - __half2float(__ushort_as_half(h1h));
        const uint32_t low = (uint32_t)f2h(r0) | ((uint32_t)f2h(r1) << 16);

        const int ks = jg >> 4;
        const int rem = jg & 15;
        const int laneW = (b & 7) * 4 + ((rem >> 1) & 3);
        const int word = (b >> 3) * 2 + ((rem >> 3) & 1);
        const int half = word >> 2, sub = word & 3;
        const size_t base =
            (((((size_t)(wb * 2 + dir) * 64 + ks) * 2) * 2 + half) * 32 + laneW) * 4 + sub;
        hpw[base] = hiw;                       // seg 0 (hi)
        hpw[base + 2 * 32 * 4] = low;          // seg 1 (lo): +1 seg = +2*32 uint4 = +256 words... (uint4=4 words -> 2*32*4)
    }
}

// ---------------------------------------------------------------------------
// hy / cy tail.  out = [ output | hy(2,B,H) | cy(2,B,H) ]
// ---------------------------------------------------------------------------
__global__ void finalize_kernel(float* __restrict__ out) {
    const int idx = blockIdx.x * blockDim.x + threadIdx.x;
    const int j = idx & (HH - 1);
    const int b = (idx >> 10) & (BB - 1);
    const int dir = idx >> 15;

    const size_t base = (size_t)TT * BB * H2;
    float h;
    if (dir == 0)
        h = out[((size_t)(TT - 1) * BB + b) * H2 + j];
    else
        h = out[((size_t)b) * H2 + HH + j];
    out[base + ((size_t)dir * BB + b) * HH + j] = h;
    out[base + 2 * BB * HH + ((size_t)dir * BB + b) * HH + j] =
        g_c[((size_t)dir * BB + b) * HH + j];
}

// ---------------------------------------------------------------------------
extern "C" void kernel_launch(void* const* d_in, const int* in_sizes, int n_in,
                              void* d_out, int out_size) {
    const float* x     = (const float*)d_in[0];
    const float* wih_f = (const float*)d_in[1];
    const float* whh_f = (const float*)d_in[2];
    const float* bih_f = (const float*)d_in[3];
    const float* bhh_f = (const float*)d_in[4];
    const float* wih_r = (const float*)d_in[5];
    const float* whh_r = (const float*)d_in[6];
    const float* bih_r = (const float*)d_in[7];
    const float* bhh_r = (const float*)d_in[8];
    float* out = (float*)d_out;

    const int gemm_smem = 8192 * 16;  // 128 KB
    cudaFuncSetAttribute(gemm_gx,
                         cudaFuncAttributeMaxDynamicSharedMemorySize, gemm_smem);

    prepack_a<<<4096, 256>>>(whh_f, whh_r);
    prepack_x<<<4000, 256>>>(x);
    prepack_wb<<<8192, 256>>>(wih_f, wih_r);
    init_kernel<<<256, 256>>>();

    gemm_gx<<<dim3(64, 125), 256, gemm_smem>>>(bih_f, bhh_f, bih_r, bhh_r);

    for (int t = 0; t < TT; ++t)
        lstm_step<<<128, 128>>>(out, t);

    finalize_kernel<<<64, 1024>>>(out);
}

// round 7
// speedup vs baseline: 7.1581x; 1.8604x over previous
#include <cuda_runtime.h>
#include <cuda_fp16.h>
#include <cstdint>

// Problem constants
#define TT 500
#define BB 32
#define INF 512
#define HH 1024
#define G4 4096
#define H2 2048
#define NBLK2 128

// gx: [dir][t][b][jp(512)][gate(4)][jj(2)]  fp32
__device__ float g_gxp[(size_t)2 * TT * BB * G4];
// W_hh fp16 A-fragments: [dir][mt(256)][kA(64)][lane(32)] uint4 ; row=4j+gate
__device__ uint4 g_ap[2 * 256 * 64 * 32];
// h fp16 B-fragments: [buf(2)][dir(2)][kA(64)][seg(2)][half(2)][lane(32)] uint4
__device__ uint4 g_hp[2 * 2 * 64 * 2 * 2 * 32];
// x fp16 A-fragments: [mt(1000)][kA(32)][lane(32)] uint4
__device__ uint4 g_xa[1000 * 32 * 32];
// w_ih fp16 B-fragments: [dir][nt(128)][kA(32)][half(2)][lane(32)] uint4
__device__ uint4 g_wb[2 * 128 * 32 * 2 * 32];
// grid barrier counter
__device__ unsigned g_count;

__device__ __forceinline__ float hsig(float x) {
    return fminf(fmaxf(0.2f * x + 0.5f, 0.0f), 1.0f);
}
__device__ __forceinline__ float htanh(float x) {
    return fminf(fmaxf(x, -1.0f), 1.0f);
}
__device__ __forceinline__ void mma16816(float* c, const uint4& a,
                                         uint32_t b0, uint32_t b1) {
    asm volatile(
        "mma.sync.aligned.m16n8k16.row.col.f32.f16.f16.f32 "
        "{%0,%1,%2,%3}, {%4,%5,%6,%7}, {%8,%9}, {%0,%1,%2,%3};"
        : "+f"(c[0]), "+f"(c[1]), "+f"(c[2]), "+f"(c[3])
        : "r"(a.x), "r"(a.y), "r"(a.z), "r"(a.w), "r"(b0), "r"(b1));
}
__device__ __forceinline__ uint32_t smaddr(const void* p) {
    uint32_t a;
    asm("{ .reg .u64 t; cvta.to.shared.u64 t, %1; cvt.u32.u64 %0, t; }"
        : "=r"(a) : "l"(p));
    return a;
}
__device__ __forceinline__ void cpa16(uint32_t s, const void* g) {
    asm volatile("cp.async.cg.shared.global [%0], [%1], 16;" :: "r"(s), "l"(g));
}
__device__ __forceinline__ void cpa_commit() {
    asm volatile("cp.async.commit_group;");
}
template <int N>
__device__ __forceinline__ void cpa_wait() {
    asm volatile("cp.async.wait_group %0;" :: "n"(N));
}
__device__ __forceinline__ uint16_t f2h(float v) {
    return __half_as_ushort(__float2half_rn(v));
}
// L1-bypassing load (persistent kernel: L1 is stale across steps for h!)
__device__ __forceinline__ uint4 ldcg(const uint4* p) {
    uint4 v;
    asm volatile("ld.global.cg.v4.u32 {%0,%1,%2,%3}, [%4];"
                 : "=r"(v.x), "=r"(v.y), "=r"(v.z), "=r"(v.w) : "l"(p));
    return v;
}

// ---------------------------------------------------------------------------
// Prepack w_hh -> fp16 A-fragments (unchanged, proven).
// ---------------------------------------------------------------------------
__global__ void prepack_a(const float* __restrict__ whh_f,
                          const float* __restrict__ whh_r) {
    const int id = blockIdx.x * blockDim.x + threadIdx.x;
    const int lane = id & 31;
    const int kA = (id >> 5) & 63;
    const int mt = (id >> 11) & 255;
    const int dir = id >> 19;
    const float* __restrict__ w = dir ? whh_r : whh_f;
    const int g = lane >> 2, tq = lane & 3;
    const int rbase = mt * 16 + g;
    const int k0 = kA * 16 + 2 * tq;

    uint32_t outw[4];
#pragma unroll
    for (int pos = 0; pos < 4; ++pos) {
        const int row = rbase + (pos & 1) * 8;
        const int kk = k0 + (pos >> 1) * 8;
        const int j = row >> 2, gate = row & 3;
        const float* wrow = w + (size_t)(gate * HH + j) * HH;
        outw[pos] = (uint32_t)f2h(wrow[kk]) | ((uint32_t)f2h(wrow[kk + 1]) << 16);
    }
    g_ap[id] = make_uint4(outw[0], outw[1], outw[2], outw[3]);
}

// ---------------------------------------------------------------------------
// Prepack x -> fp16 A-fragments (unchanged).
// ---------------------------------------------------------------------------
__global__ void prepack_x(const float* __restrict__ x) {
    const int id = blockIdx.x * blockDim.x + threadIdx.x;
    if (id >= 1000 * 32 * 32) return;
    const int lane = id & 31;
    const int kA = (id >> 5) & 31;
    const int mt = id >> 10;
    const int g = lane >> 2, tq = lane & 3;
    const int m0 = mt * 16 + g;
    const int k0 = kA * 16 + 2 * tq;

    uint32_t outw[4];
#pragma unroll
    for (int pos = 0; pos < 4; ++pos) {
        const int m = m0 + (pos & 1) * 8;
        const int kk = k0 + (pos >> 1) * 8;
        const float* xr = x + (size_t)m * INF;
        outw[pos] = (uint32_t)f2h(xr[kk]) | ((uint32_t)f2h(xr[kk + 1]) << 16);
    }
    g_xa[id] = make_uint4(outw[0], outw[1], outw[2], outw[3]);
}

// ---------------------------------------------------------------------------
// Prepack w_ih -> fp16 B-fragments (unchanged).
// ---------------------------------------------------------------------------
__global__ void prepack_wb(const float* __restrict__ wih_f,
                           const float* __restrict__ wih_r) {
    const int id = blockIdx.x * blockDim.x + threadIdx.x;
    const int sub = id & 3;
    const int laneW = (id >> 2) & 31;
    const int half = (id >> 7) & 1;
    const int kA = (id >> 8) & 31;
    const int nt = (id >> 13) & 127;
    const int dir = id >> 20;
    const float* __restrict__ w = dir ? wih_r : wih_f;

    const int wd = half * 4 + sub;
    const int ip = (wd & 1) * 4 + (laneW & 3);
    const int nl = (wd >> 1) * 8 + (laneW >> 2);
    const int n = nt * 32 + nl;
    const int k = kA * 16 + ip * 2;
    const float* wr = w + (size_t)n * INF;
    reinterpret_cast<uint32_t*>(g_wb)[id] =
        (uint32_t)f2h(wr[k]) | ((uint32_t)f2h(wr[k + 1]) << 16);
}

// ---------------------------------------------------------------------------
__global__ void init_kernel() {
    const int id = blockIdx.x * blockDim.x + threadIdx.x;
    if (id < 2 * 2 * 64 * 2 * 2 * 32) g_hp[id] = make_uint4(0u, 0u, 0u, 0u);
    if (id == 0) g_count = 0u;
}

// ---------------------------------------------------------------------------
// gx GEMM via fp16 mma.sync (unchanged, proven).
// ---------------------------------------------------------------------------
__global__ void __launch_bounds__(256)
gemm_gx(const float* __restrict__ bih_f, const float* __restrict__ bhh_f,
        const float* __restrict__ bih_r, const float* __restrict__ bhh_r) {
    extern __shared__ uint4 sm[];
    const uint32_t sbase = smaddr(sm);

    const int tid = threadIdx.x;
    const int lane = tid & 31;
    const int wid = tid >> 5;
    const int mw = wid >> 2, nw = wid & 3;
    const int dir = blockIdx.x >> 5;
    const int nti = blockIdx.x & 31;
    const int mt0 = blockIdx.y * 8;
    const int nt0 = nti * 4;

    const float* __restrict__ b1 = dir ? bih_r : bih_f;
    const float* __restrict__ b2 = dir ? bhh_r : bhh_f;
    float* __restrict__ gx = g_gxp + (size_t)dir * TT * BB * G4;

    auto load_chunk = [&](int c, int buf) {
        const int kA0 = c * 8;
#pragma unroll
        for (int i = 0; i < 8; ++i) {
            const int idx = tid + i * 256;
            const int mtl = idx >> 8;
            const int kAl = (idx >> 5) & 7;
            const int l = idx & 31;
            const uint4* src = g_xa + ((size_t)(mt0 + mtl) * 32 + kA0 + kAl) * 32 + l;
            cpa16(sbase + (buf * 2048 + idx) * 16, src);
        }
#pragma unroll
        for (int i = 0; i < 8; ++i) {
            const int idx = tid + i * 256;
            const int ntl = idx >> 9;
            const int kAl = (idx >> 6) & 7;
            const int hf = (idx >> 5) & 1;
            const int l = idx & 31;
            const uint4* src =
                g_wb + ((((size_t)(dir * 128 + nt0 + ntl) * 32 + kA0 + kAl) * 2 + hf)) * 32 + l;
            cpa16(sbase + (4096 + buf * 2048 + idx) * 16, src);
        }
        cpa_commit();
    };

    float acc[4][4][4] = {};

    load_chunk(0, 0);
    load_chunk(1, 1);

#pragma unroll 1
    for (int c = 0; c < 4; ++c) {
        cpa_wait<1>();
        __syncthreads();
        const int buf = c & 1;
        const uint4* Asm = sm + buf * 2048;
        const uint4* Bsm = sm + 4096 + buf * 2048;
#pragma unroll
        for (int kAl = 0; kAl < 8; ++kAl) {
            uint4 af[4];
#pragma unroll
            for (int i = 0; i < 4; ++i)
                af[i] = Asm[((mw * 4 + i) * 8 + kAl) * 32 + lane];
            uint4 bf0 = Bsm[((nw * 8 + kAl) * 2 + 0) * 32 + lane];
            uint4 bf1 = Bsm[((nw * 8 + kAl) * 2 + 1) * 32 + lane];
#pragma unroll
            for (int i = 0; i < 4; ++i) {
                mma16816(acc[i][0], af[i], bf0.x, bf0.y);
                mma16816(acc[i][1], af[i], bf0.z, bf0.w);
                mma16816(acc[i][2], af[i], bf1.x, bf1.y);
                mma16816(acc[i][3], af[i], bf1.z, bf1.w);
            }
        }
        __syncthreads();
        if (c + 2 < 4) load_chunk(c + 2, buf);
    }

    const int g = lane >> 2, q = lane & 3;
#pragma unroll
    for (int i = 0; i < 4; ++i) {
        const int m = blockIdx.y * 128 + mw * 64 + i * 16 + g;
#pragma unroll
        for (int nt = 0; nt < 4; ++nt) {
            const int nd = nti * 128 + nw * 32 + nt * 8 + q * 2;
            const int gate = nd >> 10;
            const int j = nd & 1023;
            const int jp = j >> 1;
            const float bias0 = __ldg(&b1[nd]) + __ldg(&b2[nd]);
            const float bias1 = __ldg(&b1[nd + 1]) + __ldg(&b2[nd + 1]);
#pragma unroll
            for (int hrow = 0; hrow < 2; ++hrow) {
                const int mm = m + hrow * 8;
                const int tt = mm >> 5, bb = mm & 31;
                float2 v = make_float2(acc[i][nt][hrow * 2] + bias0,
                                       acc[i][nt][hrow * 2 + 1] + bias1);
                *(float2*)&gx[(((size_t)tt * BB + bb) * 512 + jp) * 8 + gate * 2] = v;
            }
        }
    }
}

// ---------------------------------------------------------------------------
// Persistent weight-stationary recurrence. 128 CTAs x 256 thr (8 warps).
// CTA = (dir, ct): 64 gate-rows (16 j). Warp (r,s): rows mt=ct*4+r, K-half s.
// A-fragments register-resident for all 500 steps. K-split reduced via smem.
// ---------------------------------------------------------------------------
__global__ void __launch_bounds__(256, 1)
lstm_persist(float* __restrict__ out) {
    __shared__ float sD[2][64][33];
    const int tid = threadIdx.x;
    const int lane = tid & 31;
    const int wid = tid >> 5;
    const int r = wid & 3;
    const int s = wid >> 2;
    const int dir = blockIdx.x >> 6;
    const int ct = blockIdx.x & 63;

    // Load A fragments into registers (once).
    uint4 areg[32];
    {
        const uint4* Ap =
            g_ap + (((size_t)(dir * 256 + ct * 4 + r) * 64) + s * 32) * 32 + lane;
#pragma unroll
        for (int kk = 0; kk < 32; ++kk) areg[kk] = __ldg(Ap + kk * 32);
    }

    // Epilogue slot: thread -> (jpair jp, batch eb). State in registers.
    const int eb = tid & 31;
    const int jp = tid >> 5;          // 0..7
    const int jg = ct * 16 + jp * 2;  // global j (even)
    float2 creg = make_float2(0.f, 0.f);
    float2 hlast = make_float2(0.f, 0.f);

    uint32_t* __restrict__ hpw = reinterpret_cast<uint32_t*>(g_hp);
    const float* __restrict__ gxd = g_gxp;

#pragma unroll 1
    for (int t = 0; t < TT; ++t) {
        const int tr = dir ? (TT - 1 - t) : t;
        const int rb = t & 1, wb = rb ^ 1;
        const uint4* __restrict__ Bp =
            g_hp + (((size_t)(rb * 2 + dir) * 64) + s * 32) * 128 + lane;

        float acc[4][4] = {};
        uint4 pb0[4], pb1[4];
#pragma unroll
        for (int s2 = 0; s2 < 4; ++s2) pb0[s2] = ldcg(Bp + s2 * 32);

#pragma unroll
        for (int kq = 0; kq < 16; ++kq) {
            const int k0 = 2 * kq;
            if (k0 + 1 < 32) {
#pragma unroll
                for (int s2 = 0; s2 < 4; ++s2)
                    pb1[s2] = ldcg(Bp + (k0 + 1) * 128 + s2 * 32);
            }
            {
                const uint4 a = areg[k0];
                mma16816(acc[0], a, pb0[0].x, pb0[0].y);
                mma16816(acc[1], a, pb0[0].z, pb0[0].w);
                mma16816(acc[2], a, pb0[1].x, pb0[1].y);
                mma16816(acc[3], a, pb0[1].z, pb0[1].w);
                mma16816(acc[0], a, pb0[2].x, pb0[2].y);
                mma16816(acc[1], a, pb0[2].z, pb0[2].w);
                mma16816(acc[2], a, pb0[3].x, pb0[3].y);
                mma16816(acc[3], a, pb0[3].z, pb0[3].w);
            }
            if (k0 + 2 < 32) {
#pragma unroll
                for (int s2 = 0; s2 < 4; ++s2)
                    pb0[s2] = ldcg(Bp + (k0 + 2) * 128 + s2 * 32);
            }
            {
                const uint4 a = areg[k0 + 1];
                mma16816(acc[0], a, pb1[0].x, pb1[0].y);
                mma16816(acc[1], a, pb1[0].z, pb1[0].w);
                mma16816(acc[2], a, pb1[1].x, pb1[1].y);
                mma16816(acc[3], a, pb1[1].z, pb1[1].w);
                mma16816(acc[0], a, pb1[2].x, pb1[2].y);
                mma16816(acc[1], a, pb1[2].z, pb1[2].w);
                mma16816(acc[2], a, pb1[3].x, pb1[3].y);
                mma16816(acc[3], a, pb1[3].z, pb1[3].w);
            }
        }

        // D -> smem (per K-slice buffer).
        {
            const int g = lane >> 2, tq = lane & 3;
#pragma unroll
            for (int nt = 0; nt < 4; ++nt) {
                sD[s][r * 16 + g][nt * 8 + 2 * tq] = acc[nt][0];
                sD[s][r * 16 + g][nt * 8 + 2 * tq + 1] = acc[nt][1];
                sD[s][r * 16 + g + 8][nt * 8 + 2 * tq] = acc[nt][2];
                sD[s][r * 16 + g + 8][nt * 8 + 2 * tq + 1] = acc[nt][3];
            }
        }
        __syncthreads();

        // Epilogue: one slot per thread; reduce K-split, gates, cell update.
        {
            const int jl0 = jp * 2;
            const float* gxs =
                &gxd[((((size_t)dir * TT + tr) * BB + eb) * 512 + (ct * 8 + jp)) * 8];
            float4 x0 = *(const float4*)gxs;
            float4 x1 = *(const float4*)(gxs + 4);

            const float di0 = sD[0][jl0 * 4 + 0][eb] + sD[1][jl0 * 4 + 0][eb];
            const float df0 = sD[0][jl0 * 4 + 1][eb] + sD[1][jl0 * 4 + 1][eb];
            const float dg0 = sD[0][jl0 * 4 + 2][eb] + sD[1][jl0 * 4 + 2][eb];
            const float do0 = sD[0][jl0 * 4 + 3][eb] + sD[1][jl0 * 4 + 3][eb];
            const float di1 = sD[0][jl0 * 4 + 4][eb] + sD[1][jl0 * 4 + 4][eb];
            const float df1 = sD[0][jl0 * 4 + 5][eb] + sD[1][jl0 * 4 + 5][eb];
            const float dg1 = sD[0][jl0 * 4 + 6][eb] + sD[1][jl0 * 4 + 6][eb];
            const float do1 = sD[0][jl0 * 4 + 7][eb] + sD[1][jl0 * 4 + 7][eb];

            const float i0 = hsig(di0 + x0.x);
            const float f0 = hsig(df0 + x0.z);
            const float g0 = htanh(dg0 + x1.x);
            const float o0 = hsig(do0 + x1.z);
            const float c0 = f0 * creg.x + i0 * g0;
            const float h0 = o0 * htanh(c0);

            const float i1 = hsig(di1 + x0.y);
            const float f1 = hsig(df1 + x0.w);
            const float g1 = htanh(dg1 + x1.y);
            const float o1 = hsig(do1 + x1.w);
            const float c1 = f1 * creg.y + i1 * g1;
            const float h1 = o1 * htanh(c1);

            creg = make_float2(c0, c1);
            hlast = make_float2(h0, h1);
            *(float2*)&out[((size_t)tr * BB + eb) * H2 + dir * HH + jg] = hlast;

            // h -> fp16 B-fragments (hi + lo) into buffer wb.
            const uint16_t h0h = f2h(h0);
            const uint16_t h1h = f2h(h1);
            const uint32_t hiw = (uint32_t)h0h | ((uint32_t)h1h << 16);
            const float r0 = h0 - __half2float(__ushort_as_half(h0h));
            const float r1 = h1 - __half2float(__ushort_as_half(h1h));
            const uint32_t low = (uint32_t)f2h(r0) | ((uint32_t)f2h(r1) << 16);

            const int ks = jg >> 4;
            const int rem = jg & 15;
            const int laneW = (eb & 7) * 4 + ((rem >> 1) & 3);
            const int word = (eb >> 3) * 2 + ((rem >> 3) & 1);
            const int half = word >> 2, sub = word & 3;
            const size_t base =
                (((((size_t)(wb * 2 + dir) * 64 + ks) * 2) * 2 + half) * 32 + laneW) * 4 + sub;
            hpw[base] = hiw;           // seg 0 (hi)
            hpw[base + 256] = low;     // seg 1 (lo)
        }

        // Grid-wide barrier.
        __threadfence();
        __syncthreads();
        if (tid == 0) {
            atomicAdd(&g_count, 1u);
            const unsigned target = (unsigned)NBLK2 * (unsigned)(t + 1);
            volatile unsigned* p = &g_count;
            while (*p < target) __nanosleep(32);
            __threadfence();
        }
        __syncthreads();
    }

    // hy / cy tail.
    {
        const size_t obase = (size_t)TT * BB * H2;
        *(float2*)&out[obase + ((size_t)dir * BB + eb) * HH + jg] = hlast;
        *(float2*)&out[obase + 2 * BB * HH + ((size_t)dir * BB + eb) * HH + jg] = creg;
    }
}

// ---------------------------------------------------------------------------
extern "C" void kernel_launch(void* const* d_in, const int* in_sizes, int n_in,
                              void* d_out, int out_size) {
    const float* x     = (const float*)d_in[0];
    const float* wih_f = (const float*)d_in[1];
    const float* whh_f = (const float*)d_in[2];
    const float* bih_f = (const float*)d_in[3];
    const float* bhh_f = (const float*)d_in[4];
    const float* wih_r = (const float*)d_in[5];
    const float* whh_r = (const float*)d_in[6];
    const float* bih_r = (const float*)d_in[7];
    const float* bhh_r = (const float*)d_in[8];
    float* out = (float*)d_out;

    const int gemm_smem = 8192 * 16;  // 128 KB
    cudaFuncSetAttribute(gemm_gx,
                         cudaFuncAttributeMaxDynamicSharedMemorySize, gemm_smem);

    prepack_a<<<4096, 256>>>(whh_f, whh_r);
    prepack_x<<<4000, 256>>>(x);
    prepack_wb<<<8192, 256>>>(wih_f, wih_r);
    init_kernel<<<256, 256>>>();

    gemm_gx<<<dim3(64, 125), 256, gemm_smem>>>(bih_f, bhh_f, bih_r, bhh_r);

    lstm_persist<<<NBLK2, 256>>>(out);
}

// round 8
// speedup vs baseline: 7.7448x; 1.0820x over previous
#include <cuda_runtime.h>
#include <cuda_fp16.h>
#include <cstdint>

// Problem constants
#define TT 500
#define BB 32
#define INF 512
#define HH 1024
#define G4 4096
#define H2 2048
#define NBLK2 128

// gx: [dir][t][b][jp(512)][gate(4)][jj(2)]  fp32
__device__ float g_gxp[(size_t)2 * TT * BB * G4];
// W_hh fp16 A-fragments: [dir][mt(256)][kA(64)][lane(32)] uint4 ; row=4j+gate
__device__ uint4 g_ap[2 * 256 * 64 * 32];
// h fp16 B-fragments: [buf(2)][dir(2)][kA(64)][seg(2)][half(2)][lane(32)] uint4
__device__ uint4 g_hp[2 * 2 * 64 * 2 * 2 * 32];
// x fp16 A-fragments: [mt(1000)][kA(32)][lane(32)] uint4
__device__ uint4 g_xa[1000 * 32 * 32];
// w_ih fp16 B-fragments: [dir][nt(128)][kA(32)][half(2)][lane(32)] uint4
__device__ uint4 g_wb[2 * 128 * 32 * 2 * 32];
// grid barrier counter
__device__ unsigned g_count;

__device__ __forceinline__ float hsig(float x) {
    return fminf(fmaxf(0.2f * x + 0.5f, 0.0f), 1.0f);
}
__device__ __forceinline__ float htanh(float x) {
    return fminf(fmaxf(x, -1.0f), 1.0f);
}
__device__ __forceinline__ void mma16816(float* c, const uint4& a,
                                         uint32_t b0, uint32_t b1) {
    asm volatile(
        "mma.sync.aligned.m16n8k16.row.col.f32.f16.f16.f32 "
        "{%0,%1,%2,%3}, {%4,%5,%6,%7}, {%8,%9}, {%0,%1,%2,%3};"
        : "+f"(c[0]), "+f"(c[1]), "+f"(c[2]), "+f"(c[3])
        : "r"(a.x), "r"(a.y), "r"(a.z), "r"(a.w), "r"(b0), "r"(b1));
}
__device__ __forceinline__ uint32_t smaddr(const void* p) {
    uint32_t a;
    asm("{ .reg .u64 t; cvta.to.shared.u64 t, %1; cvt.u32.u64 %0, t; }"
        : "=r"(a) : "l"(p));
    return a;
}
__device__ __forceinline__ void cpa16(uint32_t s, const void* g) {
    asm volatile("cp.async.cg.shared.global [%0], [%1], 16;" :: "r"(s), "l"(g));
}
__device__ __forceinline__ void cpa_commit() {
    asm volatile("cp.async.commit_group;");
}
template <int N>
__device__ __forceinline__ void cpa_wait() {
    asm volatile("cp.async.wait_group %0;" :: "n"(N));
}
__device__ __forceinline__ uint16_t f2h(float v) {
    return __half_as_ushort(__float2half_rn(v));
}

// ---------------------------------------------------------------------------
// Prepack w_hh -> fp16 A-fragments (proven).
// ---------------------------------------------------------------------------
__global__ void prepack_a(const float* __restrict__ whh_f,
                          const float* __restrict__ whh_r) {
    const int id = blockIdx.x * blockDim.x + threadIdx.x;
    const int lane = id & 31;
    const int kA = (id >> 5) & 63;
    const int mt = (id >> 11) & 255;
    const int dir = id >> 19;
    const float* __restrict__ w = dir ? whh_r : whh_f;
    const int g = lane >> 2, tq = lane & 3;
    const int rbase = mt * 16 + g;
    const int k0 = kA * 16 + 2 * tq;

    uint32_t outw[4];
#pragma unroll
    for (int pos = 0; pos < 4; ++pos) {
        const int row = rbase + (pos & 1) * 8;
        const int kk = k0 + (pos >> 1) * 8;
        const int j = row >> 2, gate = row & 3;
        const float* wrow = w + (size_t)(gate * HH + j) * HH;
        outw[pos] = (uint32_t)f2h(wrow[kk]) | ((uint32_t)f2h(wrow[kk + 1]) << 16);
    }
    g_ap[id] = make_uint4(outw[0], outw[1], outw[2], outw[3]);
}

// ---------------------------------------------------------------------------
// Prepack x -> fp16 A-fragments (proven).
// ---------------------------------------------------------------------------
__global__ void prepack_x(const float* __restrict__ x) {
    const int id = blockIdx.x * blockDim.x + threadIdx.x;
    if (id >= 1000 * 32 * 32) return;
    const int lane = id & 31;
    const int kA = (id >> 5) & 31;
    const int mt = id >> 10;
    const int g = lane >> 2, tq = lane & 3;
    const int m0 = mt * 16 + g;
    const int k0 = kA * 16 + 2 * tq;

    uint32_t outw[4];
#pragma unroll
    for (int pos = 0; pos < 4; ++pos) {
        const int m = m0 + (pos & 1) * 8;
        const int kk = k0 + (pos >> 1) * 8;
        const float* xr = x + (size_t)m * INF;
        outw[pos] = (uint32_t)f2h(xr[kk]) | ((uint32_t)f2h(xr[kk + 1]) << 16);
    }
    g_xa[id] = make_uint4(outw[0], outw[1], outw[2], outw[3]);
}

// ---------------------------------------------------------------------------
// Prepack w_ih -> fp16 B-fragments (proven).
// ---------------------------------------------------------------------------
__global__ void prepack_wb(const float* __restrict__ wih_f,
                           const float* __restrict__ wih_r) {
    const int id = blockIdx.x * blockDim.x + threadIdx.x;
    const int sub = id & 3;
    const int laneW = (id >> 2) & 31;
    const int half = (id >> 7) & 1;
    const int kA = (id >> 8) & 31;
    const int nt = (id >> 13) & 127;
    const int dir = id >> 20;
    const float* __restrict__ w = dir ? wih_r : wih_f;

    const int wd = half * 4 + sub;
    const int ip = (wd & 1) * 4 + (laneW & 3);
    const int nl = (wd >> 1) * 8 + (laneW >> 2);
    const int n = nt * 32 + nl;
    const int k = kA * 16 + ip * 2;
    const float* wr = w + (size_t)n * INF;
    reinterpret_cast<uint32_t*>(g_wb)[id] =
        (uint32_t)f2h(wr[k]) | ((uint32_t)f2h(wr[k + 1]) << 16);
}

// ---------------------------------------------------------------------------
__global__ void init_kernel() {
    const int id = blockIdx.x * blockDim.x + threadIdx.x;
    if (id < 2 * 2 * 64 * 2 * 2 * 32) g_hp[id] = make_uint4(0u, 0u, 0u, 0u);
    if (id == 0) g_count = 0u;
}

// ---------------------------------------------------------------------------
// gx GEMM via fp16 mma.sync (proven, unchanged).
// ---------------------------------------------------------------------------
__global__ void __launch_bounds__(256)
gemm_gx(const float* __restrict__ bih_f, const float* __restrict__ bhh_f,
        const float* __restrict__ bih_r, const float* __restrict__ bhh_r) {
    extern __shared__ uint4 sm[];
    const uint32_t sbase = smaddr(sm);

    const int tid = threadIdx.x;
    const int lane = tid & 31;
    const int wid = tid >> 5;
    const int mw = wid >> 2, nw = wid & 3;
    const int dir = blockIdx.x >> 5;
    const int nti = blockIdx.x & 31;
    const int mt0 = blockIdx.y * 8;
    const int nt0 = nti * 4;

    const float* __restrict__ b1 = dir ? bih_r : bih_f;
    const float* __restrict__ b2 = dir ? bhh_r : bhh_f;
    float* __restrict__ gx = g_gxp + (size_t)dir * TT * BB * G4;

    auto load_chunk = [&](int c, int buf) {
        const int kA0 = c * 8;
#pragma unroll
        for (int i = 0; i < 8; ++i) {
            const int idx = tid + i * 256;
            const int mtl = idx >> 8;
            const int kAl = (idx >> 5) & 7;
            const int l = idx & 31;
            const uint4* src = g_xa + ((size_t)(mt0 + mtl) * 32 + kA0 + kAl) * 32 + l;
            cpa16(sbase + (buf * 2048 + idx) * 16, src);
        }
#pragma unroll
        for (int i = 0; i < 8; ++i) {
            const int idx = tid + i * 256;
            const int ntl = idx >> 9;
            const int kAl = (idx >> 6) & 7;
            const int hf = (idx >> 5) & 1;
            const int l = idx & 31;
            const uint4* src =
                g_wb + ((((size_t)(dir * 128 + nt0 + ntl) * 32 + kA0 + kAl) * 2 + hf)) * 32 + l;
            cpa16(sbase + (4096 + buf * 2048 + idx) * 16, src);
        }
        cpa_commit();
    };

    float acc[4][4][4] = {};

    load_chunk(0, 0);
    load_chunk(1, 1);

#pragma unroll 1
    for (int c = 0; c < 4; ++c) {
        cpa_wait<1>();
        __syncthreads();
        const int buf = c & 1;
        const uint4* Asm = sm + buf * 2048;
        const uint4* Bsm = sm + 4096 + buf * 2048;
#pragma unroll
        for (int kAl = 0; kAl < 8; ++kAl) {
            uint4 af[4];
#pragma unroll
            for (int i = 0; i < 4; ++i)
                af[i] = Asm[((mw * 4 + i) * 8 + kAl) * 32 + lane];
            uint4 bf0 = Bsm[((nw * 8 + kAl) * 2 + 0) * 32 + lane];
            uint4 bf1 = Bsm[((nw * 8 + kAl) * 2 + 1) * 32 + lane];
#pragma unroll
            for (int i = 0; i < 4; ++i) {
                mma16816(acc[i][0], af[i], bf0.x, bf0.y);
                mma16816(acc[i][1], af[i], bf0.z, bf0.w);
                mma16816(acc[i][2], af[i], bf1.x, bf1.y);
                mma16816(acc[i][3], af[i], bf1.z, bf1.w);
            }
        }
        __syncthreads();
        if (c + 2 < 4) load_chunk(c + 2, buf);
    }

    const int g = lane >> 2, q = lane & 3;
#pragma unroll
    for (int i = 0; i < 4; ++i) {
        const int m = blockIdx.y * 128 + mw * 64 + i * 16 + g;
#pragma unroll
        for (int nt = 0; nt < 4; ++nt) {
            const int nd = nti * 128 + nw * 32 + nt * 8 + q * 2;
            const int gate = nd >> 10;
            const int j = nd & 1023;
            const int jp = j >> 1;
            const float bias0 = __ldg(&b1[nd]) + __ldg(&b2[nd]);
            const float bias1 = __ldg(&b1[nd + 1]) + __ldg(&b2[nd + 1]);
#pragma unroll
            for (int hrow = 0; hrow < 2; ++hrow) {
                const int mm = m + hrow * 8;
                const int tt = mm >> 5, bb = mm & 31;
                float2 v = make_float2(acc[i][nt][hrow * 2] + bias0,
                                       acc[i][nt][hrow * 2 + 1] + bias1);
                *(float2*)&gx[(((size_t)tt * BB + bb) * 512 + jp) * 8 + gate * 2] = v;
            }
        }
    }
}

// ---------------------------------------------------------------------------
// Persistent weight-stationary recurrence, smem-staged h.
// 128 CTAs x 256 thr (8 warps). CTA = (dir, ct): 64 gate-rows.
// Warp (rg, s): row-group rg (32 rows = 2 mma tiles), K-quarter s (16 kA).
// Per step: warp-pair (rg=0,1 of same s) cp.async their 32KB h chunk to smem,
// named-barrier sync, MMA from smem fragments, 4-way K reduction via smem.
// Dynamic smem: sH[8192 uint4] (128KB) + sD[4][64][33] floats (33KB).
// ---------------------------------------------------------------------------
#define SH_U4 8192
#define PSM_BYTES (SH_U4 * 16 + 4 * 64 * 33 * 4)

__global__ void __launch_bounds__(256, 1)
lstm_persist(float* __restrict__ out) {
    extern __shared__ uint4 sm2[];
    uint4* sH = sm2;
    float* sDf = (float*)(sm2 + SH_U4);
    const uint32_t sHaddr = smaddr(sH);

    const int tid = threadIdx.x;
    const int lane = tid & 31;
    const int wid = tid >> 5;
    const int s = wid & 3;        // K-quarter
    const int rg = wid >> 2;      // row group (0: rows 0..31, 1: rows 32..63)
    const int dir = blockIdx.x >> 6;
    const int ct = blockIdx.x & 63;

    // Load A fragments into registers once: 2 row-tiles x 16 kA.
    uint4 areg[2][16];
#pragma unroll
    for (int i2 = 0; i2 < 2; ++i2) {
        const int mtl = rg * 2 + i2;
        const uint4* Ap =
            g_ap + (((size_t)(dir * 256 + ct * 4 + mtl) * 64) + s * 16) * 32 + lane;
#pragma unroll
        for (int kl = 0; kl < 16; ++kl) areg[i2][kl] = __ldg(Ap + kl * 32);
    }

    // Epilogue slot: thread -> (jpair jp, batch eb). State in registers.
    const int eb = tid & 31;
    const int jp = tid >> 5;
    const int jg = ct * 16 + jp * 2;
    float2 creg = make_float2(0.f, 0.f);
    float2 hlast = make_float2(0.f, 0.f);

    uint32_t* __restrict__ hpw = reinterpret_cast<uint32_t*>(g_hp);
    const float* __restrict__ gxd = g_gxp;

#pragma unroll 1
    for (int t = 0; t < TT; ++t) {
        const int tr = dir ? (TT - 1 - t) : t;
        const int rb = t & 1, wb = rb ^ 1;

        // Stage this warp-pair's h chunk (kA s*16 .. s*16+15) into smem.
        // Each warp loads 1024 uint4 (16KB); pair = full 32KB chunk.
        {
            const size_t gbase = (size_t)(rb * 2 + dir) * SH_U4;
            const int cbase = s * 2048 + rg * 1024;
#pragma unroll
            for (int i = 0; i < 32; ++i) {
                const int idx = cbase + i * 32 + lane;
                cpa16(sHaddr + idx * 16, g_hp + gbase + idx);
            }
            cpa_commit();
            cpa_wait<0>();
            asm volatile("bar.sync %0, 64;" :: "r"(s + 1) : "memory");
        }

        float acc[2][4][4] = {};

        // MMA over 16 kA, double-buffered smem fragment loads.
        {
            const uint4* Bq = sH + (s * 16) * 128;
            uint4 pb0[4], pb1[4];
#pragma unroll
            for (int s2 = 0; s2 < 4; ++s2) pb0[s2] = Bq[s2 * 32 + lane];
#pragma unroll
            for (int kl = 0; kl < 16; ++kl) {
                uint4* cur = (kl & 1) ? pb1 : pb0;
                uint4* nxt = (kl & 1) ? pb0 : pb1;
                if (kl + 1 < 16) {
#pragma unroll
                    for (int s2 = 0; s2 < 4; ++s2)
                        nxt[s2] = Bq[(kl + 1) * 128 + s2 * 32 + lane];
                }
#pragma unroll
                for (int i2 = 0; i2 < 2; ++i2) {
                    const uint4 a = areg[i2][kl];
                    mma16816(acc[i2][0], a, cur[0].x, cur[0].y);
                    mma16816(acc[i2][1], a, cur[0].z, cur[0].w);
                    mma16816(acc[i2][2], a, cur[1].x, cur[1].y);
                    mma16816(acc[i2][3], a, cur[1].z, cur[1].w);
                    mma16816(acc[i2][0], a, cur[2].x, cur[2].y);
                    mma16816(acc[i2][1], a, cur[2].z, cur[2].w);
                    mma16816(acc[i2][2], a, cur[3].x, cur[3].y);
                    mma16816(acc[i2][3], a, cur[3].z, cur[3].w);
                }
            }
        }

        // D -> smem (4 K-slices).
        {
            const int g = lane >> 2, tq = lane & 3;
#pragma unroll
            for (int i2 = 0; i2 < 2; ++i2) {
                const int rbse = (rg * 2 + i2) * 16;
#pragma unroll
                for (int nt = 0; nt < 4; ++nt) {
                    sDf[(s * 64 + rbse + g) * 33 + nt * 8 + 2 * tq] = acc[i2][nt][0];
                    sDf[(s * 64 + rbse + g) * 33 + nt * 8 + 2 * tq + 1] = acc[i2][nt][1];
                    sDf[(s * 64 + rbse + g + 8) * 33 + nt * 8 + 2 * tq] = acc[i2][nt][2];
                    sDf[(s * 64 + rbse + g + 8) * 33 + nt * 8 + 2 * tq + 1] = acc[i2][nt][3];
                }
            }
        }
        __syncthreads();

        // Epilogue: reduce 4 K-slices, gates, cell update, write h.
        {
            const int jl0 = jp * 2;
            const float* gxs =
                &gxd[((((size_t)dir * TT + tr) * BB + eb) * 512 + (ct * 8 + jp)) * 8];
            float4 x0 = *(const float4*)gxs;
            float4 x1 = *(const float4*)(gxs + 4);

            float d[8];
#pragma unroll
            for (int q = 0; q < 8; ++q) {
                float v = 0.f;
#pragma unroll
                for (int sl = 0; sl < 4; ++sl)
                    v += sDf[(sl * 64 + jl0 * 4 + q) * 33 + eb];
                d[q] = v;
            }

            const float i0 = hsig(d[0] + x0.x);
            const float f0 = hsig(d[1] + x0.z);
            const float g0 = htanh(d[2] + x1.x);
            const float o0 = hsig(d[3] + x1.z);
            const float c0 = f0 * creg.x + i0 * g0;
            const float h0 = o0 * htanh(c0);

            const float i1 = hsig(d[4] + x0.y);
            const float f1 = hsig(d[5] + x0.w);
            const float g1 = htanh(d[6] + x1.y);
            const float o1 = hsig(d[7] + x1.w);
            const float c1 = f1 * creg.y + i1 * g1;
            const float h1 = o1 * htanh(c1);

            creg = make_float2(c0, c1);
            hlast = make_float2(h0, h1);
            *(float2*)&out[((size_t)tr * BB + eb) * H2 + dir * HH + jg] = hlast;

            const uint16_t h0h = f2h(h0);
            const uint16_t h1h = f2h(h1);
            const uint32_t hiw = (uint32_t)h0h | ((uint32_t)h1h << 16);
            const float r0 = h0 - __half2float(__ushort_as_half(h0h));
            const float r1 = h1 - __half2float(__ushort_as_half(h1h));
            const uint32_t low = (uint32_t)f2h(r0) | ((uint32_t)f2h(r1) << 16);

            const int ks = jg >> 4;
            const int rem = jg & 15;
            const int laneW = (eb & 7) * 4 + ((rem >> 1) & 3);
            const int word = (eb >> 3) * 2 + ((rem >> 3) & 1);
            const int half = word >> 2, sub = word & 3;
            const size_t base =
                (((((size_t)(wb * 2 + dir) * 64 + ks) * 2) * 2 + half) * 32 + laneW) * 4 + sub;
            hpw[base] = hiw;           // seg 0 (hi)
            hpw[base + 256] = low;     // seg 1 (lo)
        }

        // Grid-wide barrier.
        __threadfence();
        __syncthreads();
        if (tid == 0) {
            atomicAdd(&g_count, 1u);
            const unsigned target = (unsigned)NBLK2 * (unsigned)(t + 1);
            volatile unsigned* p = &g_count;
            while (*p < target) __nanosleep(32);
            __threadfence();
        }
        __syncthreads();
    }

    // hy / cy tail.
    {
        const size_t obase = (size_t)TT * BB * H2;
        *(float2*)&out[obase + ((size_t)dir * BB + eb) * HH + jg] = hlast;
        *(float2*)&out[obase + 2 * BB * HH + ((size_t)dir * BB + eb) * HH + jg] = creg;
    }
}

// ---------------------------------------------------------------------------
extern "C" void kernel_launch(void* const* d_in, const int* in_sizes, int n_in,
                              void* d_out, int out_size) {
    const float* x     = (const float*)d_in[0];
    const float* wih_f = (const float*)d_in[1];
    const float* whh_f = (const float*)d_in[2];
    const float* bih_f = (const float*)d_in[3];
    const float* bhh_f = (const float*)d_in[4];
    const float* wih_r = (const float*)d_in[5];
    const float* whh_r = (const float*)d_in[6];
    const float* bih_r = (const float*)d_in[7];
    const float* bhh_r = (const float*)d_in[8];
    float* out = (float*)d_out;

    const int gemm_smem = 8192 * 16;  // 128 KB
    cudaFuncSetAttribute(gemm_gx,
                         cudaFuncAttributeMaxDynamicSharedMemorySize, gemm_smem);
    cudaFuncSetAttribute(lstm_persist,
                         cudaFuncAttributeMaxDynamicSharedMemorySize, PSM_BYTES);

    prepack_a<<<4096, 256>>>(whh_f, whh_r);
    prepack_x<<<4000, 256>>>(x);
    prepack_wb<<<8192, 256>>>(wih_f, wih_r);
    init_kernel<<<256, 256>>>();

    gemm_gx<<<dim3(64, 125), 256, gemm_smem>>>(bih_f, bhh_f, bih_r, bhh_r);

    lstm_persist<<<NBLK2, 256, PSM_BYTES>>>(out);
}

// round 12
// speedup vs baseline: 8.3124x; 1.0733x over previous
#include <cuda_runtime.h>
#include <cuda_fp16.h>
#include <cstdint>

// Problem constants
#define TT 500
#define BB 32
#define INF 512
#define HH 1024
#define G4 4096
#define H2 2048
#define NBLK2 128

// gx: [dir][t][b][jp(512)][gate(4)][jj(2)]  fp32
__device__ float g_gxp[(size_t)2 * TT * BB * G4];
// W_hh fp16 A-fragments: [dir][mt(256)][kA(64)][lane(32)] uint4 ; row=4j+gate
__device__ uint4 g_ap[2 * 256 * 64 * 32];
// h fp16 B-fragments: [buf(2)][dir(2)][kA(64)][seg(2)][half(2)][lane(32)] uint4
__device__ uint4 g_hp[2 * 2 * 64 * 2 * 2 * 32];
// x fp16 A-fragments: [mt(1000)][kA(32)][lane(32)] uint4
__device__ uint4 g_xa[1000 * 32 * 32];
// w_ih fp16 B-fragments: [dir][nt(128)][kA(32)][half(2)][lane(32)] uint4
__device__ uint4 g_wb[2 * 128 * 32 * 2 * 32];
// barrier state: per-direction arrival counter (padded to separate L2 lines)
__device__ unsigned g_cnt[2 * 32];

__device__ __forceinline__ float hsig(float x) {
    return fminf(fmaxf(0.2f * x + 0.5f, 0.0f), 1.0f);
}
__device__ __forceinline__ float htanh(float x) {
    return fminf(fmaxf(x, -1.0f), 1.0f);
}
__device__ __forceinline__ void mma16816(float* c, const uint4& a,
                                         uint32_t b0, uint32_t b1) {
    asm volatile(
        "mma.sync.aligned.m16n8k16.row.col.f32.f16.f16.f32 "
        "{%0,%1,%2,%3}, {%4,%5,%6,%7}, {%8,%9}, {%0,%1,%2,%3};"
        : "+f"(c[0]), "+f"(c[1]), "+f"(c[2]), "+f"(c[3])
        : "r"(a.x), "r"(a.y), "r"(a.z), "r"(a.w), "r"(b0), "r"(b1));
}
__device__ __forceinline__ uint32_t smaddr(const void* p) {
    uint32_t a;
    asm("{ .reg .u64 t; cvta.to.shared.u64 t, %1; cvt.u32.u64 %0, t; }"
        : "=r"(a) : "l"(p));
    return a;
}
__device__ __forceinline__ void cpa16(uint32_t s, const void* g) {
    asm volatile("cp.async.cg.shared.global [%0], [%1], 16;" :: "r"(s), "l"(g));
}
__device__ __forceinline__ void cpa_commit() {
    asm volatile("cp.async.commit_group;");
}
template <int N>
__device__ __forceinline__ void cpa_wait() {
    asm volatile("cp.async.wait_group %0;" :: "n"(N));
}
__device__ __forceinline__ uint16_t f2h(float v) {
    return __half_as_ushort(__float2half_rn(v));
}

// ---------------------------------------------------------------------------
// Prepack w_hh -> fp16 A-fragments (proven).
// ---------------------------------------------------------------------------
__global__ void prepack_a(const float* __restrict__ whh_f,
                          const float* __restrict__ whh_r) {
    const int id = blockIdx.x * blockDim.x + threadIdx.x;
    const int lane = id & 31;
    const int kA = (id >> 5) & 63;
    const int mt = (id >> 11) & 255;
    const int dir = id >> 19;
    const float* __restrict__ w = dir ? whh_r : whh_f;
    const int g = lane >> 2, tq = lane & 3;
    const int rbase = mt * 16 + g;
    const int k0 = kA * 16 + 2 * tq;

    uint32_t outw[4];
#pragma unroll
    for (int pos = 0; pos < 4; ++pos) {
        const int row = rbase + (pos & 1) * 8;
        const int kk = k0 + (pos >> 1) * 8;
        const int j = row >> 2, gate = row & 3;
        const float* wrow = w + (size_t)(gate * HH + j) * HH;
        outw[pos] = (uint32_t)f2h(wrow[kk]) | ((uint32_t)f2h(wrow[kk + 1]) << 16);
    }
    g_ap[id] = make_uint4(outw[0], outw[1], outw[2], outw[3]);
}

// ---------------------------------------------------------------------------
// Prepack x -> fp16 A-fragments (proven).
// ---------------------------------------------------------------------------
__global__ void prepack_x(const float* __restrict__ x) {
    const int id = blockIdx.x * blockDim.x + threadIdx.x;
    if (id >= 1000 * 32 * 32) return;
    const int lane = id & 31;
    const int kA = (id >> 5) & 31;
    const int mt = id >> 10;
    const int g = lane >> 2, tq = lane & 3;
    const int m0 = mt * 16 + g;
    const int k0 = kA * 16 + 2 * tq;

    uint32_t outw[4];
#pragma unroll
    for (int pos = 0; pos < 4; ++pos) {
        const int m = m0 + (pos & 1) * 8;
        const int kk = k0 + (pos >> 1) * 8;
        const float* xr = x + (size_t)m * INF;
        outw[pos] = (uint32_t)f2h(xr[kk]) | ((uint32_t)f2h(xr[kk + 1]) << 16);
    }
    g_xa[id] = make_uint4(outw[0], outw[1], outw[2], outw[3]);
}

// ---------------------------------------------------------------------------
// Prepack w_ih -> fp16 B-fragments (proven).
// ---------------------------------------------------------------------------
__global__ void prepack_wb(const float* __restrict__ wih_f,
                           const float* __restrict__ wih_r) {
    const int id = blockIdx.x * blockDim.x + threadIdx.x;
    const int sub = id & 3;
    const int laneW = (id >> 2) & 31;
    const int half = (id >> 7) & 1;
    const int kA = (id >> 8) & 31;
    const int nt = (id >> 13) & 127;
    const int dir = id >> 20;
    const float* __restrict__ w = dir ? wih_r : wih_f;

    const int wd = half * 4 + sub;
    const int ip = (wd & 1) * 4 + (laneW & 3);
    const int nl = (wd >> 1) * 8 + (laneW >> 2);
    const int n = nt * 32 + nl;
    const int k = kA * 16 + ip * 2;
    const float* wr = w + (size_t)n * INF;
    reinterpret_cast<uint32_t*>(g_wb)[id] =
        (uint32_t)f2h(wr[k]) | ((uint32_t)f2h(wr[k + 1]) << 16);
}

// ---------------------------------------------------------------------------
__global__ void init_kernel() {
    const int id = blockIdx.x * blockDim.x + threadIdx.x;
    if (id < 2 * 2 * 64 * 2 * 2 * 32) g_hp[id] = make_uint4(0u, 0u, 0u, 0u);
    if (id < 2 * 32) g_cnt[id] = 0u;
}

// ---------------------------------------------------------------------------
// gx GEMM via fp16 mma.sync (proven, unchanged).
// ---------------------------------------------------------------------------
__global__ void __launch_bounds__(256)
gemm_gx(const float* __restrict__ bih_f, const float* __restrict__ bhh_f,
        const float* __restrict__ bih_r, const float* __restrict__ bhh_r) {
    extern __shared__ uint4 sm[];
    const uint32_t sbase = smaddr(sm);

    const int tid = threadIdx.x;
    const int lane = tid & 31;
    const int wid = tid >> 5;
    const int mw = wid >> 2, nw = wid & 3;
    const int dir = blockIdx.x >> 5;
    const int nti = blockIdx.x & 31;
    const int mt0 = blockIdx.y * 8;
    const int nt0 = nti * 4;

    const float* __restrict__ b1 = dir ? bih_r : bih_f;
    const float* __restrict__ b2 = dir ? bhh_r : bhh_f;
    float* __restrict__ gx = g_gxp + (size_t)dir * TT * BB * G4;

    auto load_chunk = [&](int c, int buf) {
        const int kA0 = c * 8;
#pragma unroll
        for (int i = 0; i < 8; ++i) {
            const int idx = tid + i * 256;
            const int mtl = idx >> 8;
            const int kAl = (idx >> 5) & 7;
            const int l = idx & 31;
            const uint4* src = g_xa + ((size_t)(mt0 + mtl) * 32 + kA0 + kAl) * 32 + l;
            cpa16(sbase + (buf * 2048 + idx) * 16, src);
        }
#pragma unroll
        for (int i = 0; i < 8; ++i) {
            const int idx = tid + i * 256;
            const int ntl = idx >> 9;
            const int kAl = (idx >> 6) & 7;
            const int hf = (idx >> 5) & 1;
            const int l = idx & 31;
            const uint4* src =
                g_wb + ((((size_t)(dir * 128 + nt0 + ntl) * 32 + kA0 + kAl) * 2 + hf)) * 32 + l;
            cpa16(sbase + (4096 + buf * 2048 + idx) * 16, src);
        }
        cpa_commit();
    };

    float acc[4][4][4] = {};

    load_chunk(0, 0);
    load_chunk(1, 1);

#pragma unroll 1
    for (int c = 0; c < 4; ++c) {
        cpa_wait<1>();
        __syncthreads();
        const int buf = c & 1;
        const uint4* Asm = sm + buf * 2048;
        const uint4* Bsm = sm + 4096 + buf * 2048;
#pragma unroll
        for (int kAl = 0; kAl < 8; ++kAl) {
            uint4 af[4];
#pragma unroll
            for (int i = 0; i < 4; ++i)
                af[i] = Asm[((mw * 4 + i) * 8 + kAl) * 32 + lane];
            uint4 bf0 = Bsm[((nw * 8 + kAl) * 2 + 0) * 32 + lane];
            uint4 bf1 = Bsm[((nw * 8 + kAl) * 2 + 1) * 32 + lane];
#pragma unroll
            for (int i = 0; i < 4; ++i) {
                mma16816(acc[i][0], af[i], bf0.x, bf0.y);
                mma16816(acc[i][1], af[i], bf0.z, bf0.w);
                mma16816(acc[i][2], af[i], bf1.x, bf1.y);
                mma16816(acc[i][3], af[i], bf1.z, bf1.w);
            }
        }
        __syncthreads();
        if (c + 2 < 4) load_chunk(c + 2, buf);
    }

    const int g = lane >> 2, q = lane & 3;
#pragma unroll
    for (int i = 0; i < 4; ++i) {
        const int m = blockIdx.y * 128 + mw * 64 + i * 16 + g;
#pragma unroll
        for (int nt = 0; nt < 4; ++nt) {
            const int nd = nti * 128 + nw * 32 + nt * 8 + q * 2;
            const int gate = nd >> 10;
            const int j = nd & 1023;
            const int jp = j >> 1;
            const float bias0 = __ldg(&b1[nd]) + __ldg(&b2[nd]);
            const float bias1 = __ldg(&b1[nd + 1]) + __ldg(&b2[nd + 1]);
#pragma unroll
            for (int hrow = 0; hrow < 2; ++hrow) {
                const int mm = m + hrow * 8;
                const int tt = mm >> 5, bb = mm & 31;
                float2 v = make_float2(acc[i][nt][hrow * 2] + bias0,
                                       acc[i][nt][hrow * 2 + 1] + bias1);
                *(float2*)&gx[(((size_t)tt * BB + bb) * 512 + jp) * 8 + gate * 2] = v;
            }
        }
    }
}

// ---------------------------------------------------------------------------
// Persistent weight-stationary recurrence, smem-staged h.
// 128 CTAs x 256 thr. Per-direction barrier with VOLATILE counter poll
// (PTX-morally-strong, proven in R8); gx prefetched at step start.
// ---------------------------------------------------------------------------
#define SH_U4 8192
#define PSM_BYTES (SH_U4 * 16 + 4 * 64 * 33 * 4)

__global__ void __launch_bounds__(256, 1)
lstm_persist(float* __restrict__ out) {
    extern __shared__ uint4 sm2[];
    uint4* sH = sm2;
    float* sDf = (float*)(sm2 + SH_U4);
    const uint32_t sHaddr = smaddr(sH);

    const int tid = threadIdx.x;
    const int lane = tid & 31;
    const int wid = tid >> 5;
    const int s = wid & 3;        // K-quarter
    const int rg = wid >> 2;      // row group
    const int dir = blockIdx.x >> 6;
    const int ct = blockIdx.x & 63;

    // Load A fragments into registers once: 2 row-tiles x 16 kA.
    uint4 areg[2][16];
#pragma unroll
    for (int i2 = 0; i2 < 2; ++i2) {
        const int mtl = rg * 2 + i2;
        const uint4* Ap =
            g_ap + (((size_t)(dir * 256 + ct * 4 + mtl) * 64) + s * 16) * 32 + lane;
#pragma unroll
        for (int kl = 0; kl < 16; ++kl) areg[i2][kl] = __ldg(Ap + kl * 32);
    }

    // Epilogue slot: thread -> (jpair jp, batch eb).
    const int eb = tid & 31;
    const int jp = tid >> 5;
    const int jg = ct * 16 + jp * 2;
    float2 creg = make_float2(0.f, 0.f);
    float2 hlast = make_float2(0.f, 0.f);

    uint32_t* __restrict__ hpw = reinterpret_cast<uint32_t*>(g_hp);
    const float* __restrict__ gxd = g_gxp;
    unsigned* __restrict__ cntp = &g_cnt[dir * 32];

#pragma unroll 1
    for (int t = 0; t < TT; ++t) {
        const int tr = dir ? (TT - 1 - t) : t;
        const int rb = t & 1, wb = rb ^ 1;

        // gx prefetch (DRAM, ~1us) — overlaps staging + MMA below.
        const float* gxs =
            &gxd[((((size_t)dir * TT + tr) * BB + eb) * 512 + (ct * 8 + jp)) * 8];
        const float4 x0 = __ldg((const float4*)gxs);
        const float4 x1 = __ldg((const float4*)(gxs + 4));

        // Stage this warp-pair's h chunk (kA s*16..s*16+15) into smem.
        {
            const size_t gbase = (size_t)(rb * 2 + dir) * SH_U4;
            const int cbase = s * 2048 + rg * 1024;
#pragma unroll
            for (int i = 0; i < 32; ++i) {
                const int idx = cbase + i * 32 + lane;
                cpa16(sHaddr + idx * 16, g_hp + gbase + idx);
            }
            cpa_commit();
            cpa_wait<0>();
            asm volatile("bar.sync %0, 64;" :: "r"(s + 1) : "memory");
        }

        float acc[2][4][4] = {};

        // MMA over 16 kA, double-buffered smem fragment loads.
        {
            const uint4* Bq = sH + (s * 16) * 128;
            uint4 pb0[4], pb1[4];
#pragma unroll
            for (int s2 = 0; s2 < 4; ++s2) pb0[s2] = Bq[s2 * 32 + lane];
#pragma unroll
            for (int kl = 0; kl < 16; ++kl) {
                uint4* cur = (kl & 1) ? pb1 : pb0;
                uint4* nxt = (kl & 1) ? pb0 : pb1;
                if (kl + 1 < 16) {
#pragma unroll
                    for (int s2 = 0; s2 < 4; ++s2)
                        nxt[s2] = Bq[(kl + 1) * 128 + s2 * 32 + lane];
                }
#pragma unroll
                for (int i2 = 0; i2 < 2; ++i2) {
                    const uint4 a = areg[i2][kl];
                    mma16816(acc[i2][0], a, cur[0].x, cur[0].y);
                    mma16816(acc[i2][1], a, cur[0].z, cur[0].w);
                    mma16816(acc[i2][2], a, cur[1].x, cur[1].y);
                    mma16816(acc[i2][3], a, cur[1].z, cur[1].w);
                    mma16816(acc[i2][0], a, cur[2].x, cur[2].y);
                    mma16816(acc[i2][1], a, cur[2].z, cur[2].w);
                    mma16816(acc[i2][2], a, cur[3].x, cur[3].y);
                    mma16816(acc[i2][3], a, cur[3].z, cur[3].w);
                }
            }
        }

        // D -> smem (4 K-slices).
        {
            const int g = lane >> 2, tq = lane & 3;
#pragma unroll
            for (int i2 = 0; i2 < 2; ++i2) {
                const int rbse = (rg * 2 + i2) * 16;
#pragma unroll
                for (int nt = 0; nt < 4; ++nt) {
                    sDf[(s * 64 + rbse + g) * 33 + nt * 8 + 2 * tq] = acc[i2][nt][0];
                    sDf[(s * 64 + rbse + g) * 33 + nt * 8 + 2 * tq + 1] = acc[i2][nt][1];
                    sDf[(s * 64 + rbse + g + 8) * 33 + nt * 8 + 2 * tq] = acc[i2][nt][2];
                    sDf[(s * 64 + rbse + g + 8) * 33 + nt * 8 + 2 * tq + 1] = acc[i2][nt][3];
                }
            }
        }
        __syncthreads();

        // Epilogue: reduce 4 K-slices, gates, cell update, write h.
        {
            const int jl0 = jp * 2;
            float d[8];
#pragma unroll
            for (int q = 0; q < 8; ++q) {
                float v = 0.f;
#pragma unroll
                for (int sl = 0; sl < 4; ++sl)
                    v += sDf[(sl * 64 + jl0 * 4 + q) * 33 + eb];
                d[q] = v;
            }

            const float i0 = hsig(d[0] + x0.x);
            const float f0 = hsig(d[1] + x0.z);
            const float g0 = htanh(d[2] + x1.x);
            const float o0 = hsig(d[3] + x1.z);
            const float c0 = f0 * creg.x + i0 * g0;
            const float h0 = o0 * htanh(c0);

            const float i1 = hsig(d[4] + x0.y);
            const float f1 = hsig(d[5] + x0.w);
            const float g1 = htanh(d[6] + x1.y);
            const float o1 = hsig(d[7] + x1.w);
            const float c1 = f1 * creg.y + i1 * g1;
            const float h1 = o1 * htanh(c1);

            creg = make_float2(c0, c1);
            hlast = make_float2(h0, h1);

            // h -> fp16 B-fragments first (critical path for other CTAs).
            const uint16_t h0h = f2h(h0);
            const uint16_t h1h = f2h(h1);
            const uint32_t hiw = (uint32_t)h0h | ((uint32_t)h1h << 16);
            const float r0 = h0 - __half2float(__ushort_as_half(h0h));
            const float r1 = h1 - __half2float(__ushort_as_half(h1h));
            const uint32_t low = (uint32_t)f2h(r0) | ((uint32_t)f2h(r1) << 16);

            const int ks = jg >> 4;
            const int rem = jg & 15;
            const int laneW = (eb & 7) * 4 + ((rem >> 1) & 3);
            const int word = (eb >> 3) * 2 + ((rem >> 3) & 1);
            const int half = word >> 2, sub = word & 3;
            const size_t base =
                (((((size_t)(wb * 2 + dir) * 64 + ks) * 2) * 2 + half) * 32 + laneW) * 4 + sub;
            hpw[base] = hiw;           // seg 0 (hi)
            hpw[base + 256] = low;     // seg 1 (lo)

            *(float2*)&out[((size_t)tr * BB + eb) * H2 + dir * HH + jg] = hlast;
        }

        // Per-direction barrier. Arrivals RMW the counter; waiter polls the
        // SAME location with a VOLATILE load (morally-strong per PTX memory
        // model — this is the R8-proven pattern; ld.cg weak polls broke R9/R11).
        __threadfence();
        __syncthreads();
        if (tid == 0) {
            atomicAdd(cntp, 1u);
            const unsigned target = 64u * (unsigned)(t + 1);
            volatile unsigned* p = cntp;
            while (*p < target) {}
            __threadfence();
        }
        __syncthreads();
    }

    // hy / cy tail.
    {
        const size_t obase = (size_t)TT * BB * H2;
        *(float2*)&out[obase + ((size_t)dir * BB + eb) * HH + jg] = hlast;
        *(float2*)&out[obase + 2 * BB * HH + ((size_t)dir * BB + eb) * HH + jg] = creg;
    }
}

// ---------------------------------------------------------------------------
extern "C" void kernel_launch(void* const* d_in, const int* in_sizes, int n_in,
                              void* d_out, int out_size) {
    const float* x     = (const float*)d_in[0];
    const float* wih_f = (const float*)d_in[1];
    const float* whh_f = (const float*)d_in[2];
    const float* bih_f = (const float*)d_in[3];
    const float* bhh_f = (const float*)d_in[4];
    const float* wih_r = (const float*)d_in[5];
    const float* whh_r = (const float*)d_in[6];
    const float* bih_r = (const float*)d_in[7];
    const float* bhh_r = (const float*)d_in[8];
    float* out = (float*)d_out;

    const int gemm_smem = 8192 * 16;  // 128 KB
    cudaFuncSetAttribute(gemm_gx,
                         cudaFuncAttributeMaxDynamicSharedMemorySize, gemm_smem);
    cudaFuncSetAttribute(lstm_persist,
                         cudaFuncAttributeMaxDynamicSharedMemorySize, PSM_BYTES);

    prepack_a<<<4096, 256>>>(whh_f, whh_r);
    prepack_x<<<4000, 256>>>(x);
    prepack_wb<<<8192, 256>>>(wih_f, wih_r);
    init_kernel<<<256, 256>>>();

    gemm_gx<<<dim3(64, 125), 256, gemm_smem>>>(bih_f, bhh_f, bih_r, bhh_r);

    lstm_persist<<<NBLK2, 256, PSM_BYTES>>>(out);
}

// round 13
// speedup vs baseline: 8.5491x; 1.0285x over previous
#include <cuda_runtime.h>
#include <cuda_fp16.h>
#include <cstdint>

// Problem constants
#define TT 500
#define BB 32
#define INF 512
#define HH 1024
#define G4 4096
#define H2 2048
#define NBLK2 128

// gx packed fp16: [dir][t][b][jp(512)] -> uint4 of 8 halves {i0,i1,f0,f1,c0,c1,o0,o1}
__device__ uint4 g_gxh[(size_t)2 * TT * BB * 512];
// W_hh fp16 A-fragments: [dir][mt(256)][kA(64)][lane(32)] uint4 ; row=4j+gate
__device__ uint4 g_ap[2 * 256 * 64 * 32];
// h fp16 B-fragments: [buf(2)][dir(2)][kA(64)][seg(2)][half(2)][lane(32)] uint4
__device__ uint4 g_hp[2 * 2 * 64 * 2 * 2 * 32];
// x fp16 A-fragments: [mt(1000)][kA(32)][lane(32)] uint4
__device__ uint4 g_xa[1000 * 32 * 32];
// w_ih fp16 B-fragments: [dir][nt(128)][kA(32)][half(2)][lane(32)] uint4
__device__ uint4 g_wb[2 * 128 * 32 * 2 * 32];
// barrier state: per-direction arrival counter (padded to separate L2 lines)
__device__ unsigned g_cnt[2 * 32];

__device__ __forceinline__ float hsig(float x) {
    return fminf(fmaxf(0.2f * x + 0.5f, 0.0f), 1.0f);
}
__device__ __forceinline__ float htanh(float x) {
    return fminf(fmaxf(x, -1.0f), 1.0f);
}
__device__ __forceinline__ void mma16816(float* c, const uint4& a,
                                         uint32_t b0, uint32_t b1) {
    asm volatile(
        "mma.sync.aligned.m16n8k16.row.col.f32.f16.f16.f32 "
        "{%0,%1,%2,%3}, {%4,%5,%6,%7}, {%8,%9}, {%0,%1,%2,%3};"
        : "+f"(c[0]), "+f"(c[1]), "+f"(c[2]), "+f"(c[3])
        : "r"(a.x), "r"(a.y), "r"(a.z), "r"(a.w), "r"(b0), "r"(b1));
}
__device__ __forceinline__ uint32_t smaddr(const void* p) {
    uint32_t a;
    asm("{ .reg .u64 t; cvta.to.shared.u64 t, %1; cvt.u32.u64 %0, t; }"
        : "=r"(a) : "l"(p));
    return a;
}
__device__ __forceinline__ void cpa16(uint32_t s, const void* g) {
    asm volatile("cp.async.cg.shared.global [%0], [%1], 16;" :: "r"(s), "l"(g));
}
__device__ __forceinline__ void cpa_commit() {
    asm volatile("cp.async.commit_group;");
}
template <int N>
__device__ __forceinline__ void cpa_wait() {
    asm volatile("cp.async.wait_group %0;" :: "n"(N));
}
__device__ __forceinline__ uint16_t f2h(float v) {
    return __half_as_ushort(__float2half_rn(v));
}
__device__ __forceinline__ uint32_t pack2h(float a, float b) {
    return (uint32_t)f2h(a) | ((uint32_t)f2h(b) << 16);
}
__device__ __forceinline__ float2 h2f2(uint32_t u) {
    __half2 h;
    *reinterpret_cast<uint32_t*>(&h) = u;
    return __half22float2(h);
}

// ---------------------------------------------------------------------------
// Prepack w_hh -> fp16 A-fragments (proven).
// ---------------------------------------------------------------------------
__global__ void prepack_a(const float* __restrict__ whh_f,
                          const float* __restrict__ whh_r) {
    const int id = blockIdx.x * blockDim.x + threadIdx.x;
    const int lane = id & 31;
    const int kA = (id >> 5) & 63;
    const int mt = (id >> 11) & 255;
    const int dir = id >> 19;
    const float* __restrict__ w = dir ? whh_r : whh_f;
    const int g = lane >> 2, tq = lane & 3;
    const int rbase = mt * 16 + g;
    const int k0 = kA * 16 + 2 * tq;

    uint32_t outw[4];
#pragma unroll
    for (int pos = 0; pos < 4; ++pos) {
        const int row = rbase + (pos & 1) * 8;
        const int kk = k0 + (pos >> 1) * 8;
        const int j = row >> 2, gate = row & 3;
        const float* wrow = w + (size_t)(gate * HH + j) * HH;
        outw[pos] = pack2h(wrow[kk], wrow[kk + 1]);
    }
    g_ap[id] = make_uint4(outw[0], outw[1], outw[2], outw[3]);
}

// ---------------------------------------------------------------------------
// Prepack x -> fp16 A-fragments (proven).
// ---------------------------------------------------------------------------
__global__ void prepack_x(const float* __restrict__ x) {
    const int id = blockIdx.x * blockDim.x + threadIdx.x;
    if (id >= 1000 * 32 * 32) return;
    const int lane = id & 31;
    const int kA = (id >> 5) & 31;
    const int mt = id >> 10;
    const int g = lane >> 2, tq = lane & 3;
    const int m0 = mt * 16 + g;
    const int k0 = kA * 16 + 2 * tq;

    uint32_t outw[4];
#pragma unroll
    for (int pos = 0; pos < 4; ++pos) {
        const int m = m0 + (pos & 1) * 8;
        const int kk = k0 + (pos >> 1) * 8;
        const float* xr = x + (size_t)m * INF;
        outw[pos] = pack2h(xr[kk], xr[kk + 1]);
    }
    g_xa[id] = make_uint4(outw[0], outw[1], outw[2], outw[3]);
}

// ---------------------------------------------------------------------------
// Prepack w_ih -> fp16 B-fragments (proven).
// ---------------------------------------------------------------------------
__global__ void prepack_wb(const float* __restrict__ wih_f,
                           const float* __restrict__ wih_r) {
    const int id = blockIdx.x * blockDim.x + threadIdx.x;
    const int sub = id & 3;
    const int laneW = (id >> 2) & 31;
    const int half = (id >> 7) & 1;
    const int kA = (id >> 8) & 31;
    const int nt = (id >> 13) & 127;
    const int dir = id >> 20;
    const float* __restrict__ w = dir ? wih_r : wih_f;

    const int wd = half * 4 + sub;
    const int ip = (wd & 1) * 4 + (laneW & 3);
    const int nl = (wd >> 1) * 8 + (laneW >> 2);
    const int n = nt * 32 + nl;
    const int k = kA * 16 + ip * 2;
    const float* wr = w + (size_t)n * INF;
    reinterpret_cast<uint32_t*>(g_wb)[id] = pack2h(wr[k], wr[k + 1]);
}

// ---------------------------------------------------------------------------
__global__ void init_kernel() {
    const int id = blockIdx.x * blockDim.x + threadIdx.x;
    if (id < 2 * 2 * 64 * 2 * 2 * 32) g_hp[id] = make_uint4(0u, 0u, 0u, 0u);
    if (id < 2 * 32) g_cnt[id] = 0u;
}

// ---------------------------------------------------------------------------
// gx GEMM via fp16 mma.sync; epilogue stores PACKED FP16 gx.
// ---------------------------------------------------------------------------
__global__ void __launch_bounds__(256)
gemm_gx(const float* __restrict__ bih_f, const float* __restrict__ bhh_f,
        const float* __restrict__ bih_r, const float* __restrict__ bhh_r) {
    extern __shared__ uint4 sm[];
    const uint32_t sbase = smaddr(sm);

    const int tid = threadIdx.x;
    const int lane = tid & 31;
    const int wid = tid >> 5;
    const int mw = wid >> 2, nw = wid & 3;
    const int dir = blockIdx.x >> 5;
    const int nti = blockIdx.x & 31;
    const int mt0 = blockIdx.y * 8;
    const int nt0 = nti * 4;

    const float* __restrict__ b1 = dir ? bih_r : bih_f;
    const float* __restrict__ b2 = dir ? bhh_r : bhh_f;
    uint32_t* __restrict__ gxw =
        reinterpret_cast<uint32_t*>(g_gxh) + (size_t)dir * TT * BB * 2048;

    auto load_chunk = [&](int c, int buf) {
        const int kA0 = c * 8;
#pragma unroll
        for (int i = 0; i < 8; ++i) {
            const int idx = tid + i * 256;
            const int mtl = idx >> 8;
            const int kAl = (idx >> 5) & 7;
            const int l = idx & 31;
            const uint4* src = g_xa + ((size_t)(mt0 + mtl) * 32 + kA0 + kAl) * 32 + l;
            cpa16(sbase + (buf * 2048 + idx) * 16, src);
        }
#pragma unroll
        for (int i = 0; i < 8; ++i) {
            const int idx = tid + i * 256;
            const int ntl = idx >> 9;
            const int kAl = (idx >> 6) & 7;
            const int hf = (idx >> 5) & 1;
            const int l = idx & 31;
            const uint4* src =
                g_wb + ((((size_t)(dir * 128 + nt0 + ntl) * 32 + kA0 + kAl) * 2 + hf)) * 32 + l;
            cpa16(sbase + (4096 + buf * 2048 + idx) * 16, src);
        }
        cpa_commit();
    };

    float acc[4][4][4] = {};

    load_chunk(0, 0);
    load_chunk(1, 1);

#pragma unroll 1
    for (int c = 0; c < 4; ++c) {
        cpa_wait<1>();
        __syncthreads();
        const int buf = c & 1;
        const uint4* Asm = sm + buf * 2048;
        const uint4* Bsm = sm + 4096 + buf * 2048;
#pragma unroll
        for (int kAl = 0; kAl < 8; ++kAl) {
            uint4 af[4];
#pragma unroll
            for (int i = 0; i < 4; ++i)
                af[i] = Asm[((mw * 4 + i) * 8 + kAl) * 32 + lane];
            uint4 bf0 = Bsm[((nw * 8 + kAl) * 2 + 0) * 32 + lane];
            uint4 bf1 = Bsm[((nw * 8 + kAl) * 2 + 1) * 32 + lane];
#pragma unroll
            for (int i = 0; i < 4; ++i) {
                mma16816(acc[i][0], af[i], bf0.x, bf0.y);
                mma16816(acc[i][1], af[i], bf0.z, bf0.w);
                mma16816(acc[i][2], af[i], bf1.x, bf1.y);
                mma16816(acc[i][3], af[i], bf1.z, bf1.w);
            }
        }
        __syncthreads();
        if (c + 2 < 4) load_chunk(c + 2, buf);
    }

    const int g = lane >> 2, q = lane & 3;
#pragma unroll
    for (int i = 0; i < 4; ++i) {
        const int m = blockIdx.y * 128 + mw * 64 + i * 16 + g;
#pragma unroll
        for (int nt = 0; nt < 4; ++nt) {
            const int nd = nti * 128 + nw * 32 + nt * 8 + q * 2;
            const int gate = nd >> 10;
            const int j = nd & 1023;
            const int jp = j >> 1;
            const float bias0 = __ldg(&b1[nd]) + __ldg(&b2[nd]);
            const float bias1 = __ldg(&b1[nd + 1]) + __ldg(&b2[nd + 1]);
#pragma unroll
            for (int hrow = 0; hrow < 2; ++hrow) {
                const int mm = m + hrow * 8;
                const int tt = mm >> 5, bb = mm & 31;
                gxw[(((size_t)tt * BB + bb) * 512 + jp) * 4 + gate] =
                    pack2h(acc[i][nt][hrow * 2] + bias0,
                           acc[i][nt][hrow * 2 + 1] + bias1);
            }
        }
    }
}

// ---------------------------------------------------------------------------
// Persistent weight-stationary recurrence, smem-staged h.
// 128 CTAs x 256 thr. Per-direction barrier with VOLATILE counter poll
// (R12-proven). gx (fp16, one uint4/slot) prefetched ACROSS the barrier.
// ---------------------------------------------------------------------------
#define SH_U4 8192
#define PSM_BYTES (SH_U4 * 16 + 4 * 64 * 33 * 4)

__global__ void __launch_bounds__(256, 1)
lstm_persist(float* __restrict__ out) {
    extern __shared__ uint4 sm2[];
    uint4* sH = sm2;
    float* sDf = (float*)(sm2 + SH_U4);
    const uint32_t sHaddr = smaddr(sH);

    const int tid = threadIdx.x;
    const int lane = tid & 31;
    const int wid = tid >> 5;
    const int s = wid & 3;        // K-quarter
    const int rg = wid >> 2;      // row group
    const int dir = blockIdx.x >> 6;
    const int ct = blockIdx.x & 63;

    // Load A fragments into registers once: 2 row-tiles x 16 kA.
    uint4 areg[2][16];
#pragma unroll
    for (int i2 = 0; i2 < 2; ++i2) {
        const int mtl = rg * 2 + i2;
        const uint4* Ap =
            g_ap + (((size_t)(dir * 256 + ct * 4 + mtl) * 64) + s * 16) * 32 + lane;
#pragma unroll
        for (int kl = 0; kl < 16; ++kl) areg[i2][kl] = __ldg(Ap + kl * 32);
    }

    // Epilogue slot: thread -> (jpair jp, batch eb).
    const int eb = tid & 31;
    const int jp = tid >> 5;
    const int jg = ct * 16 + jp * 2;
    float2 creg = make_float2(0.f, 0.f);
    float2 hlast = make_float2(0.f, 0.f);

    uint32_t* __restrict__ hpw = reinterpret_cast<uint32_t*>(g_hp);
    const uint4* __restrict__ gxd = g_gxh + (size_t)dir * TT * BB * 512;
    unsigned* __restrict__ cntp = &g_cnt[dir * 32];

    // Prefetch gx for t = 0.
    const int slotoff = ct * 8 + jp;
    uint4 gxv;
    {
        const int tr0 = dir ? (TT - 1) : 0;
        gxv = __ldg(gxd + ((size_t)tr0 * BB + eb) * 512 + slotoff);
    }

#pragma unroll 1
    for (int t = 0; t < TT; ++t) {
        const int rb = t & 1, wb = rb ^ 1;
        const int tr = dir ? (TT - 1 - t) : t;

        // Stage this warp-pair's h chunk (kA s*16..s*16+15) into smem.
        {
            const size_t gbase = (size_t)(rb * 2 + dir) * SH_U4;
            const int cbase = s * 2048 + rg * 1024;
#pragma unroll
            for (int i = 0; i < 32; ++i) {
                const int idx = cbase + i * 32 + lane;
                cpa16(sHaddr + idx * 16, g_hp + gbase + idx);
            }
            cpa_commit();
            cpa_wait<0>();
            asm volatile("bar.sync %0, 64;" :: "r"(s + 1) : "memory");
        }

        float acc[2][4][4] = {};

        // MMA over 16 kA, double-buffered smem fragment loads.
        {
            const uint4* Bq = sH + (s * 16) * 128;
            uint4 pb0[4], pb1[4];
#pragma unroll
            for (int s2 = 0; s2 < 4; ++s2) pb0[s2] = Bq[s2 * 32 + lane];
#pragma unroll
            for (int kl = 0; kl < 16; ++kl) {
                uint4* cur = (kl & 1) ? pb1 : pb0;
                uint4* nxt = (kl & 1) ? pb0 : pb1;
                if (kl + 1 < 16) {
#pragma unroll
                    for (int s2 = 0; s2 < 4; ++s2)
                        nxt[s2] = Bq[(kl + 1) * 128 + s2 * 32 + lane];
                }
#pragma unroll
                for (int i2 = 0; i2 < 2; ++i2) {
                    const uint4 a = areg[i2][kl];
                    mma16816(acc[i2][0], a, cur[0].x, cur[0].y);
                    mma16816(acc[i2][1], a, cur[0].z, cur[0].w);
                    mma16816(acc[i2][2], a, cur[1].x, cur[1].y);
                    mma16816(acc[i2][3], a, cur[1].z, cur[1].w);
                    mma16816(acc[i2][0], a, cur[2].x, cur[2].y);
                    mma16816(acc[i2][1], a, cur[2].z, cur[2].w);
                    mma16816(acc[i2][2], a, cur[3].x, cur[3].y);
                    mma16816(acc[i2][3], a, cur[3].z, cur[3].w);
                }
            }
        }

        // D -> smem (4 K-slices).
        {
            const int g = lane >> 2, tq = lane & 3;
#pragma unroll
            for (int i2 = 0; i2 < 2; ++i2) {
                const int rbse = (rg * 2 + i2) * 16;
#pragma unroll
                for (int nt = 0; nt < 4; ++nt) {
                    sDf[(s * 64 + rbse + g) * 33 + nt * 8 + 2 * tq] = acc[i2][nt][0];
                    sDf[(s * 64 + rbse + g) * 33 + nt * 8 + 2 * tq + 1] = acc[i2][nt][1];
                    sDf[(s * 64 + rbse + g + 8) * 33 + nt * 8 + 2 * tq] = acc[i2][nt][2];
                    sDf[(s * 64 + rbse + g + 8) * 33 + nt * 8 + 2 * tq + 1] = acc[i2][nt][3];
                }
            }
        }
        __syncthreads();

        // Epilogue: reduce 4 K-slices, gates, cell update, write h.
        {
            const int jl0 = jp * 2;
            float d[8];
#pragma unroll
            for (int q = 0; q < 8; ++q) {
                float v = 0.f;
#pragma unroll
                for (int sl = 0; sl < 4; ++sl)
                    v += sDf[(sl * 64 + jl0 * 4 + q) * 33 + eb];
                d[q] = v;
            }

            const float2 xi = h2f2(gxv.x);
            const float2 xf = h2f2(gxv.y);
            const float2 xg = h2f2(gxv.z);
            const float2 xo = h2f2(gxv.w);

            const float i0 = hsig(d[0] + xi.x);
            const float f0 = hsig(d[1] + xf.x);
            const float g0 = htanh(d[2] + xg.x);
            const float o0 = hsig(d[3] + xo.x);
            const float c0 = f0 * creg.x + i0 * g0;
            const float h0 = o0 * htanh(c0);

            const float i1 = hsig(d[4] + xi.y);
            const float f1 = hsig(d[5] + xf.y);
            const float g1 = htanh(d[6] + xg.y);
            const float o1 = hsig(d[7] + xo.y);
            const float c1 = f1 * creg.y + i1 * g1;
            const float h1 = o1 * htanh(c1);

            creg = make_float2(c0, c1);
            hlast = make_float2(h0, h1);

            // h -> fp16 B-fragments first (critical path for other CTAs).
            const uint32_t hiw = pack2h(h0, h1);
            const float r0 = h0 - __half2float(__float2half_rn(h0));
            const float r1 = h1 - __half2float(__float2half_rn(h1));
            const uint32_t low = pack2h(r0, r1);

            const int ks = jg >> 4;
            const int rem = jg & 15;
            const int laneW = (eb & 7) * 4 + ((rem >> 1) & 3);
            const int word = (eb >> 3) * 2 + ((rem >> 3) & 1);
            const int half = word >> 2, sub = word & 3;
            const size_t base =
                (((((size_t)(wb * 2 + dir) * 64 + ks) * 2) * 2 + half) * 32 + laneW) * 4 + sub;
            hpw[base] = hiw;           // seg 0 (hi)
            hpw[base + 256] = low;     // seg 1 (lo)

            *(float2*)&out[((size_t)tr * BB + eb) * H2 + dir * HH + jg] = hlast;
        }

        // Prefetch next step's gx BEFORE the barrier (gx is constant data,
        // independent of h) — its DRAM latency overlaps the barrier wait.
        {
            const int tn = (t + 1 < TT) ? t + 1 : t;
            const int trn = dir ? (TT - 1 - tn) : tn;
            gxv = __ldg(gxd + ((size_t)trn * BB + eb) * 512 + slotoff);
        }

        // Per-direction barrier. Arrivals RMW the counter; waiter polls the
        // SAME location with a VOLATILE load (morally-strong per PTX memory
        // model — R12-proven; weak ld.cg polls broke R9/R11).
        __threadfence();
        __syncthreads();
        if (tid == 0) {
            atomicAdd(cntp, 1u);
            const unsigned target = 64u * (unsigned)(t + 1);
            volatile unsigned* p = cntp;
            while (*p < target) {}
            __threadfence();
        }
        __syncthreads();
    }

    // hy / cy tail.
    {
        const size_t obase = (size_t)TT * BB * H2;
        *(float2*)&out[obase + ((size_t)dir * BB + eb) * HH + jg] = hlast;
        *(float2*)&out[obase + 2 * BB * HH + ((size_t)dir * BB + eb) * HH + jg] = creg;
    }
}

// ---------------------------------------------------------------------------
extern "C" void kernel_launch(void* const* d_in, const int* in_sizes, int n_in,
                              void* d_out, int out_size) {
    const float* x     = (const float*)d_in[0];
    const float* wih_f = (const float*)d_in[1];
    const float* whh_f = (const float*)d_in[2];
    const float* bih_f = (const float*)d_in[3];
    const float* bhh_f = (const float*)d_in[4];
    const float* wih_r = (const float*)d_in[5];
    const float* whh_r = (const float*)d_in[6];
    const float* bih_r = (const float*)d_in[7];
    const float* bhh_r = (const float*)d_in[8];
    float* out = (float*)d_out;

    const int gemm_smem = 8192 * 16;  // 128 KB
    cudaFuncSetAttribute(gemm_gx,
                         cudaFuncAttributeMaxDynamicSharedMemorySize, gemm_smem);
    cudaFuncSetAttribute(lstm_persist,
                         cudaFuncAttributeMaxDynamicSharedMemorySize, PSM_BYTES);

    prepack_a<<<4096, 256>>>(whh_f, whh_r);
    prepack_x<<<4000, 256>>>(x);
    prepack_wb<<<8192, 256>>>(wih_f, wih_r);
    init_kernel<<<256, 256>>>();

    gemm_gx<<<dim3(64, 125), 256, gemm_smem>>>(bih_f, bhh_f, bih_r, bhh_r);

    lstm_persist<<<NBLK2, 256, PSM_BYTES>>>(out);
}